// round 3
// baseline (speedup 1.0000x reference)
#include <cuda_runtime.h>
#include <cstdint>

#define T_STEPS 64
#define B_ENV   128
#define L_TOK   64
#define E_DIM   256
#define H_DIM   32
#define N_TOT   (T_STEPS * B_ENV)   // 8192

// ---- device-global scratch (no runtime allocation allowed) ----
__device__ float g_M[E_DIM * E_DIM];        // M = Wq^T Wk
__device__ float g_WeffT[E_DIM * E_DIM];    // WeffT[j][f] = sum_e Wout[f,e] Wv[e,j]
__device__ float g_wihT[E_DIM * 4 * H_DIM]; // w_ih transposed [e][g]
__device__ float g_bias[4 * H_DIM];         // b_ih + b_hh
__device__ float g_hidden[(size_t)N_TOT * E_DIM];  // 8 MB
__device__ float g_xg[(size_t)N_TOT * 4 * H_DIM];  // 4 MB
__device__ int   g_mask_mode;                       // 0=int32, 1=uint8, 2=float32
__device__ float g_df[(size_t)N_TOT * L_TOK];       // dropped flags (1.0 = dropped)

// =====================================================================
// Mask dtype detection + expansion (robust to int32 / uint8 / float32)
// =====================================================================
__global__ void detect_mask_kernel(const void* __restrict__ mask) {
    __shared__ int s_f32, s_gt1;
    if (threadIdx.x == 0) { s_f32 = 0; s_gt1 = 0; }
    __syncthreads();
    const unsigned* w = (const unsigned*)mask;
    // Scan 4096 words (16 KB) — safely within the smallest possible buffer
    // (uint8: 512 KB). Bool data as 0/1 bytes or 0/1 ints can never produce
    // 0x3F800000; fp32 1.0 always does (mask has ~50% ones in first rows).
    int f32 = 0, gt1 = 0;
    for (int i = threadIdx.x; i < 4096; i += blockDim.x) {
        unsigned v = w[i];
        if (v == 0x3F800000u) f32 = 1;
        if (v > 1u) gt1 = 1;
    }
    if (f32) atomicOr(&s_f32, 1);
    if (gt1) atomicOr(&s_gt1, 1);
    __syncthreads();
    if (threadIdx.x == 0)
        g_mask_mode = s_f32 ? 2 : (s_gt1 ? 1 : 0);
}

__global__ void expand_mask_kernel(const void* __restrict__ mask) {
    int i = blockIdx.x * 256 + threadIdx.x;  // N_TOT * L_TOK = 524288
    int mode = g_mask_mode;
    bool attend;
    if (mode == 0)      attend = ((const int*)mask)[i] != 0;
    else if (mode == 1) attend = ((const uint8_t*)mask)[i] != 0;
    else                attend = ((const float*)mask)[i] != 0.f;
    g_df[i] = attend ? 0.f : 1.f;
}

// =====================================================================
// Prep kernels (tiny, run once per launch)
// =====================================================================
__global__ void prep_M(const float* __restrict__ ipw) {
    int i = blockIdx.x, j = threadIdx.x;
    float acc = 0.f;
#pragma unroll 8
    for (int e = 0; e < E_DIM; e++)
        acc += ipw[e * E_DIM + i] * ipw[(E_DIM + e) * E_DIM + j];
    g_M[i * E_DIM + j] = acc;
}

__global__ void prep_Weff(const float* __restrict__ ipw, const float* __restrict__ opw) {
    int j = blockIdx.x, f = threadIdx.x;
    float acc = 0.f;
#pragma unroll 8
    for (int e = 0; e < E_DIM; e++)
        acc += opw[f * E_DIM + e] * ipw[(2 * E_DIM + e) * E_DIM + j];
    g_WeffT[j * E_DIM + f] = acc;
}

__global__ void prep_wih(const float* __restrict__ wih,
                         const float* __restrict__ bih,
                         const float* __restrict__ bhh) {
    int idx = blockIdx.x * 256 + threadIdx.x;  // 32768 total
    int g = idx / E_DIM, e = idx % E_DIM;
    g_wihT[e * 128 + g] = wih[idx];
    if (idx < 128) g_bias[idx] = bih[idx] + bhh[idx];
}

// =====================================================================
// Attention kernel: one block per sample n.
//   scores = (x M x^T)/16, softmax, colsum -> wgt
//   hidden = (wgt^T x) @ WeffT
// =====================================================================
#define XS_STRIDE 66     // x transposed [256][66]  (pad: conflict-free + 8B align)
#define TS_STRIDE 264    // t = x@M     [64][264]   (pad: float4-aligned rows)
#define SC_STRIDE 66     // scores      [64][66]

#define OFF_XS 0
#define OFF_TS (256 * XS_STRIDE)                 // 16896
#define OFF_SC (OFF_TS + 64 * TS_STRIDE)         // 33792
#define OFF_WG (OFF_SC + 64 * SC_STRIDE)         // 38016
#define OFF_XW (OFF_WG + 64)                     // 38080
#define OFF_DF (OFF_XW + 256)                    // 38336
#define SMEM_FLOATS (OFF_DF + 64)                // 38400 -> 153600 B

__global__ void __launch_bounds__(256) attn_kernel(const float* __restrict__ x) {
    extern __shared__ float sm[];
    float* xsT = sm + OFF_XS;
    float* ts  = sm + OFF_TS;
    float* sc  = sm + OFF_SC;
    float* wgt = sm + OFF_WG;
    float* xw  = sm + OFF_XW;
    float* df  = sm + OFF_DF;

    const int n   = blockIdx.x;
    const int tid = threadIdx.x;
    const float* xb = x + (size_t)n * (L_TOK * E_DIM);

    // ---- load x transposed: xsT[j][l] ----
    for (int idx = tid; idx < L_TOK * E_DIM; idx += 256) {
        int l = idx >> 8, j = idx & 255;
        xsT[j * XS_STRIDE + l] = xb[idx];
    }
    if (tid < 64) {
        df[tid]  = g_df[(size_t)n * L_TOK + tid];  // dropped flag
        wgt[tid] = 0.f;
    }
    __syncthreads();

    // ---- phase 2: ts[l][j] = sum_i xsT[i][l] * M[i][j]  (packed f32x2, l-pairs) ----
    {
        const int jg = tid & 31, lg = tid >> 5;
        const int j0 = jg * 8, l0 = lg * 8;
        unsigned long long acc[4][8];
#pragma unroll
        for (int p = 0; p < 4; p++)
#pragma unroll
            for (int q = 0; q < 8; q++) acc[p][q] = 0ull;

        const float* Mp = g_M + j0;
#pragma unroll 4
        for (int i = 0; i < E_DIM; i++) {
            const unsigned long long* xrow =
                (const unsigned long long*)(xsT + i * XS_STRIDE + l0);
            unsigned long long a0 = xrow[0], a1 = xrow[1], a2 = xrow[2], a3 = xrow[3];
            float4 b0 = *(const float4*)(Mp + i * E_DIM);
            float4 b1 = *(const float4*)(Mp + i * E_DIM + 4);
            float bs[8] = {b0.x, b0.y, b0.z, b0.w, b1.x, b1.y, b1.z, b1.w};
#pragma unroll
            for (int q = 0; q < 8; q++) {
                unsigned long long bb;
                asm("mov.b64 %0, {%1, %1};" : "=l"(bb) : "f"(bs[q]));
                asm("fma.rn.f32x2 %0, %1, %2, %0;" : "+l"(acc[0][q]) : "l"(a0), "l"(bb));
                asm("fma.rn.f32x2 %0, %1, %2, %0;" : "+l"(acc[1][q]) : "l"(a1), "l"(bb));
                asm("fma.rn.f32x2 %0, %1, %2, %0;" : "+l"(acc[2][q]) : "l"(a2), "l"(bb));
                asm("fma.rn.f32x2 %0, %1, %2, %0;" : "+l"(acc[3][q]) : "l"(a3), "l"(bb));
            }
        }
#pragma unroll
        for (int p = 0; p < 4; p++)
#pragma unroll
            for (int q = 0; q < 8; q++) {
                float lo, hi;
                asm("mov.b64 {%0, %1}, %2;" : "=f"(lo), "=f"(hi) : "l"(acc[p][q]));
                ts[(l0 + 2 * p)     * TS_STRIDE + j0 + q] = lo;
                ts[(l0 + 2 * p + 1) * TS_STRIDE + j0 + q] = hi;
            }
    }
    __syncthreads();

    // ---- scores: sc[lq][lk] = (sum_j ts[lq][j] * xsT[j][lk]) / 16 ----
    {
        const int tx = tid & 15, ty = tid >> 4;
        const int lk0 = tx * 4, lq0 = ty * 4;
        unsigned long long acc[4][2];
#pragma unroll
        for (int c = 0; c < 4; c++) { acc[c][0] = 0ull; acc[c][1] = 0ull; }

#pragma unroll 2
        for (int j = 0; j < E_DIM; j++) {
            const unsigned long long* krow =
                (const unsigned long long*)(xsT + j * XS_STRIDE + lk0);
            unsigned long long kk0 = krow[0], kk1 = krow[1];
#pragma unroll
            for (int c = 0; c < 4; c++) {
                float tv = ts[(lq0 + c) * TS_STRIDE + j];
                unsigned long long tt;
                asm("mov.b64 %0, {%1, %1};" : "=l"(tt) : "f"(tv));
                asm("fma.rn.f32x2 %0, %1, %2, %0;" : "+l"(acc[c][0]) : "l"(tt), "l"(kk0));
                asm("fma.rn.f32x2 %0, %1, %2, %0;" : "+l"(acc[c][1]) : "l"(tt), "l"(kk1));
            }
        }
        const float scale = 0.0625f;  // 1/sqrt(256)
#pragma unroll
        for (int c = 0; c < 4; c++)
#pragma unroll
            for (int p = 0; p < 2; p++) {
                float lo, hi;
                asm("mov.b64 {%0, %1}, %2;" : "=f"(lo), "=f"(hi) : "l"(acc[c][p]));
                sc[(lq0 + c) * SC_STRIDE + lk0 + 2 * p]     = lo * scale;
                sc[(lq0 + c) * SC_STRIDE + lk0 + 2 * p + 1] = hi * scale;
            }
    }
    __syncthreads();

    // ---- softmax per row + column-sum weights ----
    {
        const int w = tid >> 5, lane = tid & 31;
        const bool dk0 = df[lane] > 0.5f, dk1 = df[lane + 32] > 0.5f;
        float wacc0 = 0.f, wacc1 = 0.f;
#pragma unroll
        for (int r = 0; r < 8; r++) {
            int lq = w * 8 + r;
            bool dq = df[lq] > 0.5f;
            float s0 = sc[lq * SC_STRIDE + lane];
            float s1 = sc[lq * SC_STRIDE + lane + 32];
            if (dq && dk0) s0 = -1e30f;
            if (dq && dk1) s1 = -1e30f;
            float m = fmaxf(s0, s1);
#pragma unroll
            for (int o = 16; o; o >>= 1) m = fmaxf(m, __shfl_xor_sync(0xffffffffu, m, o));
            float e0 = __expf(s0 - m), e1 = __expf(s1 - m);
            float ssum = e0 + e1;
#pragma unroll
            for (int o = 16; o; o >>= 1) ssum += __shfl_xor_sync(0xffffffffu, ssum, o);
            float inv = 1.f / ssum;
            wacc0 += e0 * inv;
            wacc1 += e1 * inv;
        }
        atomicAdd(&wgt[lane], wacc0);
        atomicAdd(&wgt[lane + 32], wacc1);
    }
    __syncthreads();

    // ---- xw[j] = sum_k wgt[k] * x[k][j] ----
    {
        float acc = 0.f;
#pragma unroll 8
        for (int k = 0; k < L_TOK; k++)
            acc += wgt[k] * xsT[tid * XS_STRIDE + k];
        xw[tid] = acc;
    }
    __syncthreads();

    // ---- hidden[f] = sum_j xw[j] * WeffT[j][f] ----
    {
        float acc = 0.f;
        const float* Wp = g_WeffT + tid;
#pragma unroll 8
        for (int j = 0; j < E_DIM; j++)
            acc += xw[j] * Wp[(size_t)j * E_DIM];
        g_hidden[(size_t)n * E_DIM + tid] = acc;
    }
}

// =====================================================================
// xg = hidden @ w_ih^T + (b_ih + b_hh) : one block per 8 rows
// =====================================================================
__global__ void __launch_bounds__(256) gates_in_kernel() {
    __shared__ float hsm[8 * E_DIM];
    const int n0 = blockIdx.x * 8;
    const int tid = threadIdx.x;
    for (int idx = tid; idx < 8 * E_DIM; idx += 256)
        hsm[idx] = g_hidden[(size_t)n0 * E_DIM + idx];
    __syncthreads();

    const int g = tid & 127, half = tid >> 7;
    float acc[4];
    float bz = g_bias[g];
#pragma unroll
    for (int r = 0; r < 4; r++) acc[r] = bz;

#pragma unroll 4
    for (int e = 0; e < E_DIM; e++) {
        float wv = g_wihT[e * 128 + g];
#pragma unroll
        for (int r = 0; r < 4; r++)
            acc[r] += wv * hsm[(half + 2 * r) * E_DIM + e];
    }
#pragma unroll
    for (int r = 0; r < 4; r++)
        g_xg[(size_t)(n0 + half + 2 * r) * 128 + g] = acc[r];
}

// =====================================================================
// LSTM scan + critic. Each warp owns ONE env (b): h,c register-resident,
// shfl-broadcast recurrence. 16 blocks x 8 warps = 128 envs.
// =====================================================================
__device__ __forceinline__ float sigmoidf_(float v) {
    return 1.f / (1.f + __expf(-v));
}

__global__ void __launch_bounds__(256) lstm_kernel(const float* __restrict__ done,
                                                   const float* __restrict__ h0,
                                                   const float* __restrict__ c0,
                                                   const float* __restrict__ whh,
                                                   const float* __restrict__ cw,
                                                   const float* __restrict__ cb,
                                                   float* __restrict__ out) {
    __shared__ float whs[32 * 128];  // whs[m][g] = w_hh[g][m]
    const int tid = threadIdx.x, lane = tid & 31, w = tid >> 5;
    const int b = blockIdx.x * 8 + w;

    for (int idx = tid; idx < 4096; idx += 256) {
        int g = idx >> 5, m = idx & 31;
        whs[m * 128 + g] = whh[idx];
    }
    __syncthreads();

    float h = h0[b * H_DIM + lane];
    float c = c0[b * H_DIM + lane];
    const float cwv = cw[lane];
    const float cbv = cb[0];

    for (int t = 0; t < T_STEPS; t++) {
        const int n = t * B_ENV + b;
        const float keep = 1.f - done[n];
        h *= keep;
        c *= keep;
        const float* xgp = g_xg + (size_t)n * 128;
        float ai = xgp[lane];
        float af = xgp[32 + lane];
        float ag = xgp[64 + lane];
        float ao = xgp[96 + lane];
#pragma unroll
        for (int m = 0; m < 32; m++) {
            float hv = __shfl_sync(0xffffffffu, h, m);
            ai += hv * whs[m * 128 + lane];
            af += hv * whs[m * 128 + 32 + lane];
            ag += hv * whs[m * 128 + 64 + lane];
            ao += hv * whs[m * 128 + 96 + lane];
        }
        float gi = sigmoidf_(ai);
        float gf = sigmoidf_(af);
        float gg = tanhf(ag);
        float go = sigmoidf_(ao);
        c = gf * c + gi * gg;
        h = go * tanhf(c);

        float pv = h * cwv;
#pragma unroll
        for (int o = 16; o; o >>= 1) pv += __shfl_xor_sync(0xffffffffu, pv, o);
        if (lane == 0) out[n] = pv + cbv;
    }
}

// =====================================================================
// kernel_launch
// =====================================================================
extern "C" void kernel_launch(void* const* d_in, const int* in_sizes, int n_in,
                              void* d_out, int out_size) {
    const float* x    = (const float*)d_in[0];
    const float* done = (const float*)d_in[1];
    const void*  mask = d_in[2];
    const float* h0   = (const float*)d_in[3];
    const float* c0   = (const float*)d_in[4];
    const float* ipw  = (const float*)d_in[5];
    const float* opw  = (const float*)d_in[6];
    const float* wih  = (const float*)d_in[7];
    const float* whh  = (const float*)d_in[8];
    const float* bih  = (const float*)d_in[9];
    const float* bhh  = (const float*)d_in[10];
    const float* cw   = (const float*)d_in[11];
    const float* cb   = (const float*)d_in[12];
    float*       out  = (float*)d_out;

    (void)in_sizes; (void)n_in; (void)out_size;

    static_assert(SMEM_FLOATS * 4 == 153600, "smem layout");
    cudaFuncSetAttribute(attn_kernel, cudaFuncAttributeMaxDynamicSharedMemorySize,
                         SMEM_FLOATS * 4);

    detect_mask_kernel<<<1, 256>>>(mask);
    expand_mask_kernel<<<(N_TOT * L_TOK) / 256, 256>>>(mask);
    prep_M<<<E_DIM, E_DIM>>>(ipw);
    prep_Weff<<<E_DIM, E_DIM>>>(ipw, opw);
    prep_wih<<<128, 256>>>(wih, bih, bhh);
    attn_kernel<<<N_TOT, 256, SMEM_FLOATS * 4>>>(x);
    gates_in_kernel<<<N_TOT / 8, 256>>>();
    lstm_kernel<<<16, 256>>>(done, h0, c0, whh, cw, cb, out);
}

// round 4
// speedup vs baseline: 1.0017x; 1.0017x over previous
#include <cuda_runtime.h>
#include <cstdint>

#define T_STEPS 64
#define B_ENV   128
#define L_TOK   64
#define E_DIM   256
#define H_DIM   32
#define N_TOT   (T_STEPS * B_ENV)   // 8192

// ---- device-global scratch (no runtime allocation allowed) ----
__device__ float g_M[E_DIM * E_DIM];        // M = Wq^T Wk
__device__ float g_WeffT[E_DIM * E_DIM];    // WeffT[j][f] = sum_e Wout[f,e] Wv[e,j]
__device__ float g_wihT[E_DIM * 4 * H_DIM]; // w_ih transposed [e][g]
__device__ float g_bias[4 * H_DIM];         // b_ih + b_hh
__device__ float g_hidden[(size_t)N_TOT * E_DIM];  // 8 MB
__device__ float g_xg[(size_t)N_TOT * 4 * H_DIM];  // 4 MB
__device__ int   g_mask_mode;                       // 0=int32, 1=uint8, 2=float32
__device__ float g_df[(size_t)N_TOT * L_TOK];       // dropped flags (1.0 = dropped)

// =====================================================================
// Mask dtype detection + expansion (robust to int32 / uint8 / float32)
// =====================================================================
__global__ void detect_mask_kernel(const void* __restrict__ mask) {
    __shared__ int s_f32, s_gt1;
    if (threadIdx.x == 0) { s_f32 = 0; s_gt1 = 0; }
    __syncthreads();
    const unsigned* w = (const unsigned*)mask;
    // Scan 4096 words (16 KB) — safely within the smallest possible buffer
    // (uint8: 512 KB). Bool data as 0/1 bytes or 0/1 ints can never produce
    // 0x3F800000; fp32 1.0 always does (mask has ~50% ones in first rows).
    int f32 = 0, gt1 = 0;
    for (int i = threadIdx.x; i < 4096; i += blockDim.x) {
        unsigned v = w[i];
        if (v == 0x3F800000u) f32 = 1;
        if (v > 1u) gt1 = 1;
    }
    if (f32) atomicOr(&s_f32, 1);
    if (gt1) atomicOr(&s_gt1, 1);
    __syncthreads();
    if (threadIdx.x == 0)
        g_mask_mode = s_f32 ? 2 : (s_gt1 ? 1 : 0);
}

__global__ void expand_mask_kernel(const void* __restrict__ mask) {
    int i = blockIdx.x * 256 + threadIdx.x;  // N_TOT * L_TOK = 524288
    int mode = g_mask_mode;
    bool attend;
    if (mode == 0)      attend = ((const int*)mask)[i] != 0;
    else if (mode == 1) attend = ((const uint8_t*)mask)[i] != 0;
    else                attend = ((const float*)mask)[i] != 0.f;
    g_df[i] = attend ? 0.f : 1.f;
}

// =====================================================================
// Prep kernels (tiny, run once per launch)
// =====================================================================
__global__ void prep_M(const float* __restrict__ ipw) {
    int i = blockIdx.x, j = threadIdx.x;
    float acc = 0.f;
#pragma unroll 8
    for (int e = 0; e < E_DIM; e++)
        acc += ipw[e * E_DIM + i] * ipw[(E_DIM + e) * E_DIM + j];
    g_M[i * E_DIM + j] = acc;
}

__global__ void prep_Weff(const float* __restrict__ ipw, const float* __restrict__ opw) {
    int j = blockIdx.x, f = threadIdx.x;
    float acc = 0.f;
#pragma unroll 8
    for (int e = 0; e < E_DIM; e++)
        acc += opw[f * E_DIM + e] * ipw[(2 * E_DIM + e) * E_DIM + j];
    g_WeffT[j * E_DIM + f] = acc;
}

__global__ void prep_wih(const float* __restrict__ wih,
                         const float* __restrict__ bih,
                         const float* __restrict__ bhh) {
    int idx = blockIdx.x * 256 + threadIdx.x;  // 32768 total
    int g = idx / E_DIM, e = idx % E_DIM;
    g_wihT[e * 128 + g] = wih[idx];
    if (idx < 128) g_bias[idx] = bih[idx] + bhh[idx];
}

// =====================================================================
// Attention kernel: one block per sample n.
//   scores = (x M x^T)/16, softmax, colsum -> wgt
//   hidden = (wgt^T x) @ WeffT
// =====================================================================
#define XS_STRIDE 66     // x transposed [256][66]  (pad: conflict-free + 8B align)
#define TS_STRIDE 264    // t = x@M     [64][264]   (pad: float4-aligned rows)
#define SC_STRIDE 66     // scores      [64][66]

#define OFF_XS 0
#define OFF_TS (256 * XS_STRIDE)                 // 16896
#define OFF_SC (OFF_TS + 64 * TS_STRIDE)         // 33792
#define OFF_WG (OFF_SC + 64 * SC_STRIDE)         // 38016
#define OFF_XW (OFF_WG + 64)                     // 38080
#define OFF_DF (OFF_XW + 256)                    // 38336
#define SMEM_FLOATS (OFF_DF + 64)                // 38400 -> 153600 B

__global__ void __launch_bounds__(256) attn_kernel(const float* __restrict__ x) {
    extern __shared__ float sm[];
    float* xsT = sm + OFF_XS;
    float* ts  = sm + OFF_TS;
    float* sc  = sm + OFF_SC;
    float* wgt = sm + OFF_WG;
    float* xw  = sm + OFF_XW;
    float* df  = sm + OFF_DF;

    const int n   = blockIdx.x;
    const int tid = threadIdx.x;
    const float* xb = x + (size_t)n * (L_TOK * E_DIM);

    // ---- load x transposed: xsT[j][l] ----
    for (int idx = tid; idx < L_TOK * E_DIM; idx += 256) {
        int l = idx >> 8, j = idx & 255;
        xsT[j * XS_STRIDE + l] = xb[idx];
    }
    if (tid < 64) {
        df[tid]  = g_df[(size_t)n * L_TOK + tid];  // dropped flag
        wgt[tid] = 0.f;
    }
    __syncthreads();

    // ---- phase 2: ts[l][j] = sum_i xsT[i][l] * M[i][j]  (packed f32x2, l-pairs) ----
    {
        const int jg = tid & 31, lg = tid >> 5;
        const int j0 = jg * 8, l0 = lg * 8;
        unsigned long long acc[4][8];
#pragma unroll
        for (int p = 0; p < 4; p++)
#pragma unroll
            for (int q = 0; q < 8; q++) acc[p][q] = 0ull;

        const float* Mp = g_M + j0;
#pragma unroll 4
        for (int i = 0; i < E_DIM; i++) {
            const unsigned long long* xrow =
                (const unsigned long long*)(xsT + i * XS_STRIDE + l0);
            unsigned long long a0 = xrow[0], a1 = xrow[1], a2 = xrow[2], a3 = xrow[3];
            float4 b0 = *(const float4*)(Mp + i * E_DIM);
            float4 b1 = *(const float4*)(Mp + i * E_DIM + 4);
            float bs[8] = {b0.x, b0.y, b0.z, b0.w, b1.x, b1.y, b1.z, b1.w};
#pragma unroll
            for (int q = 0; q < 8; q++) {
                unsigned long long bb;
                asm("mov.b64 %0, {%1, %1};" : "=l"(bb) : "f"(bs[q]));
                asm("fma.rn.f32x2 %0, %1, %2, %0;" : "+l"(acc[0][q]) : "l"(a0), "l"(bb));
                asm("fma.rn.f32x2 %0, %1, %2, %0;" : "+l"(acc[1][q]) : "l"(a1), "l"(bb));
                asm("fma.rn.f32x2 %0, %1, %2, %0;" : "+l"(acc[2][q]) : "l"(a2), "l"(bb));
                asm("fma.rn.f32x2 %0, %1, %2, %0;" : "+l"(acc[3][q]) : "l"(a3), "l"(bb));
            }
        }
#pragma unroll
        for (int p = 0; p < 4; p++)
#pragma unroll
            for (int q = 0; q < 8; q++) {
                float lo, hi;
                asm("mov.b64 {%0, %1}, %2;" : "=f"(lo), "=f"(hi) : "l"(acc[p][q]));
                ts[(l0 + 2 * p)     * TS_STRIDE + j0 + q] = lo;
                ts[(l0 + 2 * p + 1) * TS_STRIDE + j0 + q] = hi;
            }
    }
    __syncthreads();

    // ---- scores: sc[lq][lk] = (sum_j ts[lq][j] * xsT[j][lk]) / 16 ----
    {
        const int tx = tid & 15, ty = tid >> 4;
        const int lk0 = tx * 4, lq0 = ty * 4;
        unsigned long long acc[4][2];
#pragma unroll
        for (int c = 0; c < 4; c++) { acc[c][0] = 0ull; acc[c][1] = 0ull; }

#pragma unroll 2
        for (int j = 0; j < E_DIM; j++) {
            const unsigned long long* krow =
                (const unsigned long long*)(xsT + j * XS_STRIDE + lk0);
            unsigned long long kk0 = krow[0], kk1 = krow[1];
#pragma unroll
            for (int c = 0; c < 4; c++) {
                float tv = ts[(lq0 + c) * TS_STRIDE + j];
                unsigned long long tt;
                asm("mov.b64 %0, {%1, %1};" : "=l"(tt) : "f"(tv));
                asm("fma.rn.f32x2 %0, %1, %2, %0;" : "+l"(acc[c][0]) : "l"(tt), "l"(kk0));
                asm("fma.rn.f32x2 %0, %1, %2, %0;" : "+l"(acc[c][1]) : "l"(tt), "l"(kk1));
            }
        }
        const float scale = 0.0625f;  // 1/sqrt(256)
#pragma unroll
        for (int c = 0; c < 4; c++)
#pragma unroll
            for (int p = 0; p < 2; p++) {
                float lo, hi;
                asm("mov.b64 {%0, %1}, %2;" : "=f"(lo), "=f"(hi) : "l"(acc[c][p]));
                sc[(lq0 + c) * SC_STRIDE + lk0 + 2 * p]     = lo * scale;
                sc[(lq0 + c) * SC_STRIDE + lk0 + 2 * p + 1] = hi * scale;
            }
    }
    __syncthreads();

    // ---- softmax per row + column-sum weights ----
    {
        const int w = tid >> 5, lane = tid & 31;
        const bool dk0 = df[lane] > 0.5f, dk1 = df[lane + 32] > 0.5f;
        float wacc0 = 0.f, wacc1 = 0.f;
#pragma unroll
        for (int r = 0; r < 8; r++) {
            int lq = w * 8 + r;
            bool dq = df[lq] > 0.5f;
            float s0 = sc[lq * SC_STRIDE + lane];
            float s1 = sc[lq * SC_STRIDE + lane + 32];
            if (dq && dk0) s0 = -1e30f;
            if (dq && dk1) s1 = -1e30f;
            float m = fmaxf(s0, s1);
#pragma unroll
            for (int o = 16; o; o >>= 1) m = fmaxf(m, __shfl_xor_sync(0xffffffffu, m, o));
            float e0 = __expf(s0 - m), e1 = __expf(s1 - m);
            float ssum = e0 + e1;
#pragma unroll
            for (int o = 16; o; o >>= 1) ssum += __shfl_xor_sync(0xffffffffu, ssum, o);
            float inv = 1.f / ssum;
            wacc0 += e0 * inv;
            wacc1 += e1 * inv;
        }
        atomicAdd(&wgt[lane], wacc0);
        atomicAdd(&wgt[lane + 32], wacc1);
    }
    __syncthreads();

    // ---- xw[j] = sum_k wgt[k] * x[k][j] ----
    {
        float acc = 0.f;
#pragma unroll 8
        for (int k = 0; k < L_TOK; k++)
            acc += wgt[k] * xsT[tid * XS_STRIDE + k];
        xw[tid] = acc;
    }
    __syncthreads();

    // ---- hidden[f] = sum_j xw[j] * WeffT[j][f] ----
    {
        float acc = 0.f;
        const float* Wp = g_WeffT + tid;
#pragma unroll 8
        for (int j = 0; j < E_DIM; j++)
            acc += xw[j] * Wp[(size_t)j * E_DIM];
        g_hidden[(size_t)n * E_DIM + tid] = acc;
    }
}

// =====================================================================
// xg = hidden @ w_ih^T + (b_ih + b_hh) : one block per 8 rows
// =====================================================================
__global__ void __launch_bounds__(256) gates_in_kernel() {
    __shared__ float hsm[8 * E_DIM];
    const int n0 = blockIdx.x * 8;
    const int tid = threadIdx.x;
    for (int idx = tid; idx < 8 * E_DIM; idx += 256)
        hsm[idx] = g_hidden[(size_t)n0 * E_DIM + idx];
    __syncthreads();

    const int g = tid & 127, half = tid >> 7;
    float acc[4];
    float bz = g_bias[g];
#pragma unroll
    for (int r = 0; r < 4; r++) acc[r] = bz;

#pragma unroll 4
    for (int e = 0; e < E_DIM; e++) {
        float wv = g_wihT[e * 128 + g];
#pragma unroll
        for (int r = 0; r < 4; r++)
            acc[r] += wv * hsm[(half + 2 * r) * E_DIM + e];
    }
#pragma unroll
    for (int r = 0; r < 4; r++)
        g_xg[(size_t)(n0 + half + 2 * r) * 128 + g] = acc[r];
}

// =====================================================================
// LSTM scan + critic. Each warp owns ONE env (b): h,c register-resident,
// shfl-broadcast recurrence. 16 blocks x 8 warps = 128 envs.
// =====================================================================
__device__ __forceinline__ float sigmoidf_(float v) {
    return 1.f / (1.f + __expf(-v));
}

__global__ void __launch_bounds__(256) lstm_kernel(const float* __restrict__ done,
                                                   const float* __restrict__ h0,
                                                   const float* __restrict__ c0,
                                                   const float* __restrict__ whh,
                                                   const float* __restrict__ cw,
                                                   const float* __restrict__ cb,
                                                   float* __restrict__ out) {
    __shared__ float whs[32 * 128];  // whs[m][g] = w_hh[g][m]
    const int tid = threadIdx.x, lane = tid & 31, w = tid >> 5;
    const int b = blockIdx.x * 8 + w;

    for (int idx = tid; idx < 4096; idx += 256) {
        int g = idx >> 5, m = idx & 31;
        whs[m * 128 + g] = whh[idx];
    }
    __syncthreads();

    float h = h0[b * H_DIM + lane];
    float c = c0[b * H_DIM + lane];
    const float cwv = cw[lane];
    const float cbv = cb[0];

    for (int t = 0; t < T_STEPS; t++) {
        const int n = t * B_ENV + b;
        const float keep = 1.f - done[n];
        h *= keep;
        c *= keep;
        const float* xgp = g_xg + (size_t)n * 128;
        float ai = xgp[lane];
        float af = xgp[32 + lane];
        float ag = xgp[64 + lane];
        float ao = xgp[96 + lane];
#pragma unroll
        for (int m = 0; m < 32; m++) {
            float hv = __shfl_sync(0xffffffffu, h, m);
            ai += hv * whs[m * 128 + lane];
            af += hv * whs[m * 128 + 32 + lane];
            ag += hv * whs[m * 128 + 64 + lane];
            ao += hv * whs[m * 128 + 96 + lane];
        }
        float gi = sigmoidf_(ai);
        float gf = sigmoidf_(af);
        float gg = tanhf(ag);
        float go = sigmoidf_(ao);
        c = gf * c + gi * gg;
        h = go * tanhf(c);

        float pv = h * cwv;
#pragma unroll
        for (int o = 16; o; o >>= 1) pv += __shfl_xor_sync(0xffffffffu, pv, o);
        if (lane == 0) out[n] = pv + cbv;
    }
}

// =====================================================================
// kernel_launch
// =====================================================================
extern "C" void kernel_launch(void* const* d_in, const int* in_sizes, int n_in,
                              void* d_out, int out_size) {
    const float* x    = (const float*)d_in[0];
    const float* done = (const float*)d_in[1];
    const void*  mask = d_in[2];
    const float* h0   = (const float*)d_in[3];
    const float* c0   = (const float*)d_in[4];
    const float* ipw  = (const float*)d_in[5];
    const float* opw  = (const float*)d_in[6];
    const float* wih  = (const float*)d_in[7];
    const float* whh  = (const float*)d_in[8];
    const float* bih  = (const float*)d_in[9];
    const float* bhh  = (const float*)d_in[10];
    const float* cw   = (const float*)d_in[11];
    const float* cb   = (const float*)d_in[12];
    float*       out  = (float*)d_out;

    (void)in_sizes; (void)n_in; (void)out_size;

    static_assert(SMEM_FLOATS * 4 == 153600, "smem layout");
    cudaFuncSetAttribute(attn_kernel, cudaFuncAttributeMaxDynamicSharedMemorySize,
                         SMEM_FLOATS * 4);

    detect_mask_kernel<<<1, 256>>>(mask);
    expand_mask_kernel<<<(N_TOT * L_TOK) / 256, 256>>>(mask);
    prep_M<<<E_DIM, E_DIM>>>(ipw);
    prep_Weff<<<E_DIM, E_DIM>>>(ipw, opw);
    prep_wih<<<128, 256>>>(wih, bih, bhh);
    attn_kernel<<<N_TOT, 256, SMEM_FLOATS * 4>>>(x);
    gates_in_kernel<<<N_TOT / 8, 256>>>();
    lstm_kernel<<<16, 256>>>(done, h0, c0, whh, cw, cb, out);
}

// round 6
// speedup vs baseline: 1.3557x; 1.3534x over previous
#include <cuda_runtime.h>
#include <cuda_bf16.h>
#include <cstdint>

#define T_STEPS 64
#define B_ENV 128
#define L_TOK 64
#define E_DIM 256
#define H_DIM 32
#define N_TOT (T_STEPS * B_ENV)

__device__ float g_M[65536];
__device__ float g_WeffT[65536];
__device__ float g_W2[32768];
__device__ float g_bias[128];
__device__ unsigned short g_MtH[65536]; // bf16 hi of M^T [j][i]
__device__ unsigned short g_MtL[65536]; // bf16 lo
__device__ float g_xg[(size_t)N_TOT * 128];
__device__ float g_df[(size_t)N_TOT * 64];

// ---------------- warp MMA helpers (arch-portable, sm_80+) ----------------
__device__ __forceinline__ uint32_t smem_u32(const void* p) {
    uint32_t a;
    asm("{ .reg .u64 t; cvta.to.shared.u64 t, %1; cvt.u32.u64 %0, t; }" : "=r"(a) : "l"(p));
    return a;
}
__device__ __forceinline__ void ldm4(uint32_t* r, uint32_t a) {
    asm volatile("ldmatrix.sync.aligned.m8n8.x4.shared.b16 {%0,%1,%2,%3}, [%4];"
        : "=r"(r[0]), "=r"(r[1]), "=r"(r[2]), "=r"(r[3]) : "r"(a));
}
__device__ __forceinline__ void ldm2(uint32_t* r, uint32_t a) {
    asm volatile("ldmatrix.sync.aligned.m8n8.x2.shared.b16 {%0,%1}, [%2];"
        : "=r"(r[0]), "=r"(r[1]) : "r"(a));
}
__device__ __forceinline__ void mma_bf16(float* d, const uint32_t* a, const uint32_t* b) {
    asm volatile("mma.sync.aligned.m16n8k16.row.col.f32.bf16.bf16.f32 "
        "{%0,%1,%2,%3}, {%4,%5,%6,%7}, {%8,%9}, {%0,%1,%2,%3};"
        : "+f"(d[0]), "+f"(d[1]), "+f"(d[2]), "+f"(d[3])
        : "r"(a[0]), "r"(a[1]), "r"(a[2]), "r"(a[3]), "r"(b[0]), "r"(b[1]));
}
__device__ __forceinline__ uint32_t pack_bf2(__nv_bfloat16 lo, __nv_bfloat16 hi) {
    __nv_bfloat162 p = __halves2bfloat162(lo, hi);
    return *(uint32_t*)&p;
}

// ---------------- mask expand (per-block dtype detect) ----------------
__global__ void __launch_bounds__(256) expand_mask(const void* __restrict__ mask) {
    __shared__ int sf, sg;
    if (!threadIdx.x) { sf = 0; sg = 0; }
    __syncthreads();
    const unsigned* w = (const unsigned*)mask;
    int f = 0, g = 0;
    for (int i = threadIdx.x; i < 2048; i += 256) {
        unsigned v = w[i];
        if (v == 0x3F800000u) f = 1;
        if (v > 1u) g = 1;
    }
    if (f) atomicOr(&sf, 1);
    if (g) atomicOr(&sg, 1);
    __syncthreads();
    int mode = sf ? 2 : (sg ? 1 : 0);
    int i = blockIdx.x * 256 + threadIdx.x;
    bool at;
    if (mode == 0)      at = ((const int*)mask)[i] != 0;
    else if (mode == 1) at = ((const uint8_t*)mask)[i] != 0;
    else                at = ((const float*)mask)[i] != 0.f;
    g_df[i] = at ? 0.f : 1.f;
}

// ---------------- prep1: M (b<64), WeffT (b>=64) ----------------
__global__ void __launch_bounds__(256) prep1(const float* __restrict__ ipw, const float* __restrict__ opw) {
    __shared__ float As[32][33], Bs[32][33];
    const int b = blockIdx.x, tid = threadIdx.x, tx = tid & 31, ty = tid >> 5;
    float acc[4] = {0.f, 0.f, 0.f, 0.f};
    if (b < 64) {
        int i0 = (b >> 3) * 32, j0 = (b & 7) * 32;
        const float *Wq = ipw, *Wk = ipw + 65536;
        for (int e0 = 0; e0 < 256; e0 += 32) {
#pragma unroll
            for (int r = 0; r < 4; r++) {
                int e = ty + 8 * r;
                As[e][tx] = Wq[(e0 + e) * 256 + i0 + tx];
                Bs[e][tx] = Wk[(e0 + e) * 256 + j0 + tx];
            }
            __syncthreads();
#pragma unroll 8
            for (int e = 0; e < 32; e++) {
                float bv = Bs[e][tx];
#pragma unroll
                for (int r = 0; r < 4; r++) acc[r] += As[e][ty + 8 * r] * bv;
            }
            __syncthreads();
        }
#pragma unroll
        for (int r = 0; r < 4; r++) g_M[(i0 + ty + 8 * r) * 256 + j0 + tx] = acc[r];
    } else {
        int t = b - 64, j0 = (t >> 3) * 32, f0 = (t & 7) * 32;
        const float* Wv = ipw + 131072;
        for (int e0 = 0; e0 < 256; e0 += 32) {
#pragma unroll
            for (int r = 0; r < 4; r++) {
                int e = ty + 8 * r;
                As[e][tx] = Wv[(e0 + e) * 256 + j0 + tx];
                Bs[tx][e] = opw[(f0 + e) * 256 + e0 + tx];
            }
            __syncthreads();
#pragma unroll 8
            for (int e = 0; e < 32; e++) {
                float bv = Bs[e][tx];
#pragma unroll
                for (int r = 0; r < 4; r++) acc[r] += As[e][ty + 8 * r] * bv;
            }
            __syncthreads();
        }
#pragma unroll
        for (int r = 0; r < 4; r++) g_WeffT[(j0 + ty + 8 * r) * 256 + f0 + tx] = acc[r];
    }
}

// ---------------- prep2: Mt split (b<64), W2 (64..95), bias (96) ----------------
__global__ void __launch_bounds__(256) prep2(const float* __restrict__ wih,
                                             const float* __restrict__ bih,
                                             const float* __restrict__ bhh) {
    __shared__ float As[32][33], Bs[32][33];
    const int b = blockIdx.x, tid = threadIdx.x, tx = tid & 31, ty = tid >> 5;
    if (b < 64) {
        int i0 = (b >> 3) * 32, j0 = (b & 7) * 32;
#pragma unroll
        for (int r = 0; r < 4; r++) As[ty + 8 * r][tx] = g_M[(i0 + ty + 8 * r) * 256 + j0 + tx];
        __syncthreads();
#pragma unroll
        for (int r = 0; r < 4; r++) {
            int jj = ty + 8 * r;
            float v = As[tx][jj];
            __nv_bfloat16 h = __float2bfloat16_rn(v);
            __nv_bfloat16 l = __float2bfloat16_rn(v - __bfloat162float(h));
            g_MtH[(j0 + jj) * 256 + i0 + tx] = *(unsigned short*)&h;
            g_MtL[(j0 + jj) * 256 + i0 + tx] = *(unsigned short*)&l;
        }
        return;
    }
    if (b < 96) {
        int t = b - 64, j0 = (t >> 2) * 32, g0 = (t & 3) * 32;
        float acc[4] = {0.f, 0.f, 0.f, 0.f};
        for (int f0 = 0; f0 < 256; f0 += 32) {
#pragma unroll
            for (int r = 0; r < 4; r++) {
                int e = ty + 8 * r;
                As[tx][e] = g_WeffT[(j0 + e) * 256 + f0 + tx];
                Bs[tx][e] = wih[(g0 + e) * 256 + f0 + tx];
            }
            __syncthreads();
#pragma unroll 8
            for (int f = 0; f < 32; f++) {
                float bv = Bs[f][tx];
#pragma unroll
                for (int r = 0; r < 4; r++) acc[r] += As[f][ty + 8 * r] * bv;
            }
            __syncthreads();
        }
#pragma unroll
        for (int r = 0; r < 4; r++) g_W2[(j0 + ty + 8 * r) * 128 + g0 + tx] = acc[r];
        return;
    }
    if (tid < 128) g_bias[tid] = bih[tid] + bhh[tid];
}

// ---------------- attention: 1 sample/CTA, mma.sync split-bf16 ----------------
// smem rows: 264 bf16 = 528 B (conflict-free ldmatrix)
#define ROWB 528
#define XH_OFF  0
#define XL_OFF  33792
#define TSH_OFF 67584
#define TSL_OFF 101376
#define STG_OFF 135168
#define SC_OFF  135168     /* f32 [64][68], overlays STG after GEMM1 */
#define DF_OFF  168960
#define WGT_OFF 169216
#define XW_OFF  169472
#define SMEM_SZ 170496

__global__ void __launch_bounds__(256, 1) attn_mma(const float* __restrict__ x) {
    extern __shared__ char smem[];
    const uint32_t sb = smem_u32(smem);
    const int tid = threadIdx.x, lane = tid & 31, w = tid >> 5;
    const int n = blockIdx.x;
    float* dfp = (float*)(smem + DF_OFF);
    float* wgt = (float*)(smem + WGT_OFF);
    float* xw  = (float*)(smem + XW_OFF);
    float* sc  = (float*)(smem + SC_OFF);

    // load x [64][256] f32 -> bf16 hi/lo smem
    const float* xb = x + (size_t)n * (L_TOK * E_DIM);
    for (int idx = tid; idx < 8192; idx += 256) {
        int row = idx >> 7, cp = idx & 127;
        float2 v = ((const float2*)xb)[idx];
        __nv_bfloat16 h0 = __float2bfloat16_rn(v.x), h1 = __float2bfloat16_rn(v.y);
        __nv_bfloat16 l0 = __float2bfloat16_rn(v.x - __bfloat162float(h0));
        __nv_bfloat16 l1 = __float2bfloat16_rn(v.y - __bfloat162float(h1));
        uint32_t boff = (uint32_t)(row * ROWB + cp * 4);
        *(uint32_t*)(smem + XH_OFF + boff) = pack_bf2(h0, h1);
        *(uint32_t*)(smem + XL_OFF + boff) = pack_bf2(l0, l1);
    }
    if (tid < 64) { dfp[tid] = g_df[(size_t)n * 64 + tid]; wgt[tid] = 0.f; }

    const int mg = w >> 2, ng = w & 3;   // warp tile: rows mg*32+[0,32), cols ng*16+[0,16)
    const uint32_t arow = (uint32_t)((mg * 32 + (lane & 15)) * ROWB + ((lane >> 4) << 4));
    const uint32_t brow = (uint32_t)((ng * 16 + (lane & 7)) * ROWB + (((lane >> 3) & 1) << 4));
    const uint32_t xh_b = sb + XH_OFF, xl_b = sb + XL_OFF, st_b = sb + STG_OFF;
    const uint32_t tsh_b = sb + TSH_OFF, tsl_b = sb + TSL_OFF;

    // ---- GEMM1: ts[64][256] = x @ M, per 64-col chunk ----
    for (int ch = 0; ch < 4; ch++) {
        __syncthreads();
        {   // stage MtH chunk [64][256]
            const uint32_t* src = (const uint32_t*)g_MtH + ch * 64 * 128;
            for (int u = tid; u < 8192; u += 256)
                *(uint32_t*)(smem + STG_OFF + (u >> 7) * ROWB + (u & 127) * 4) = src[u];
        }
        __syncthreads();
        float acc[2][2][4];
#pragma unroll
        for (int a = 0; a < 2; a++)
#pragma unroll
            for (int bq = 0; bq < 2; bq++)
#pragma unroll
                for (int q = 0; q < 4; q++) acc[a][bq][q] = 0.f;

#pragma unroll 4
        for (int ks = 0; ks < 16; ks++) {
            uint32_t kb = ks * 32;
            uint32_t Ah[2][4], Al[2][4], B[2][2];
#pragma unroll
            for (int mt = 0; mt < 2; mt++) {
                ldm4(Ah[mt], xh_b + arow + mt * (16 * ROWB) + kb);
                ldm4(Al[mt], xl_b + arow + mt * (16 * ROWB) + kb);
            }
#pragma unroll
            for (int nt = 0; nt < 2; nt++) ldm2(B[nt], st_b + brow + nt * (8 * ROWB) + kb);
#pragma unroll
            for (int mt = 0; mt < 2; mt++)
#pragma unroll
                for (int nt = 0; nt < 2; nt++) {
                    mma_bf16(acc[mt][nt], Ah[mt], B[nt]);
                    mma_bf16(acc[mt][nt], Al[mt], B[nt]);
                }
        }
        __syncthreads();
        {   // stage MtL chunk
            const uint32_t* src = (const uint32_t*)g_MtL + ch * 64 * 128;
            for (int u = tid; u < 8192; u += 256)
                *(uint32_t*)(smem + STG_OFF + (u >> 7) * ROWB + (u & 127) * 4) = src[u];
        }
        __syncthreads();
#pragma unroll 4
        for (int ks = 0; ks < 16; ks++) {
            uint32_t kb = ks * 32;
            uint32_t Ah[2][4], B[2][2];
#pragma unroll
            for (int mt = 0; mt < 2; mt++) ldm4(Ah[mt], xh_b + arow + mt * (16 * ROWB) + kb);
#pragma unroll
            for (int nt = 0; nt < 2; nt++) ldm2(B[nt], st_b + brow + nt * (8 * ROWB) + kb);
#pragma unroll
            for (int mt = 0; mt < 2; mt++)
#pragma unroll
                for (int nt = 0; nt < 2; nt++) mma_bf16(acc[mt][nt], Ah[mt], B[nt]);
        }
        // store ts tile as bf16 hi/lo (c-frag layout: rows t/4, t/4+8; cols 2(t%4))
#pragma unroll
        for (int mt = 0; mt < 2; mt++)
#pragma unroll
            for (int nt = 0; nt < 2; nt++) {
                int col = ch * 64 + ng * 16 + nt * 8 + 2 * (lane & 3);
                int r0 = mg * 32 + mt * 16 + (lane >> 2);
#pragma unroll
                for (int hh = 0; hh < 2; hh++) {
                    float v0 = acc[mt][nt][2 * hh], v1 = acc[mt][nt][2 * hh + 1];
                    __nv_bfloat16 h0 = __float2bfloat16_rn(v0), h1 = __float2bfloat16_rn(v1);
                    __nv_bfloat16 l0 = __float2bfloat16_rn(v0 - __bfloat162float(h0));
                    __nv_bfloat16 l1 = __float2bfloat16_rn(v1 - __bfloat162float(h1));
                    uint32_t boff = (uint32_t)((r0 + 8 * hh) * ROWB + col * 2);
                    *(uint32_t*)(smem + TSH_OFF + boff) = pack_bf2(h0, h1);
                    *(uint32_t*)(smem + TSL_OFF + boff) = pack_bf2(l0, l1);
                }
            }
    }
    __syncthreads();

    // ---- GEMM2: sc[64][64] = ts @ x^T (3 terms) ----
    {
        float acc[2][2][4];
#pragma unroll
        for (int a = 0; a < 2; a++)
#pragma unroll
            for (int bq = 0; bq < 2; bq++)
#pragma unroll
                for (int q = 0; q < 4; q++) acc[a][bq][q] = 0.f;
#pragma unroll 2
        for (int ks = 0; ks < 16; ks++) {
            uint32_t kb = ks * 32;
            uint32_t Ah[2][4], Al[2][4], Bh[2][2], Bl[2][2];
#pragma unroll
            for (int mt = 0; mt < 2; mt++) {
                ldm4(Ah[mt], tsh_b + arow + mt * (16 * ROWB) + kb);
                ldm4(Al[mt], tsl_b + arow + mt * (16 * ROWB) + kb);
            }
#pragma unroll
            for (int nt = 0; nt < 2; nt++) {
                ldm2(Bh[nt], xh_b + brow + nt * (8 * ROWB) + kb);
                ldm2(Bl[nt], xl_b + brow + nt * (8 * ROWB) + kb);
            }
#pragma unroll
            for (int mt = 0; mt < 2; mt++)
#pragma unroll
                for (int nt = 0; nt < 2; nt++) {
                    mma_bf16(acc[mt][nt], Ah[mt], Bh[nt]);
                    mma_bf16(acc[mt][nt], Al[mt], Bh[nt]);
                    mma_bf16(acc[mt][nt], Ah[mt], Bl[nt]);
                }
        }
#pragma unroll
        for (int mt = 0; mt < 2; mt++)
#pragma unroll
            for (int nt = 0; nt < 2; nt++) {
                int col = ng * 16 + nt * 8 + 2 * (lane & 3);
                int r0 = mg * 32 + mt * 16 + (lane >> 2);
                sc[r0 * 68 + col]       = acc[mt][nt][0] * 0.0625f;
                sc[r0 * 68 + col + 1]   = acc[mt][nt][1] * 0.0625f;
                sc[(r0 + 8) * 68 + col]     = acc[mt][nt][2] * 0.0625f;
                sc[(r0 + 8) * 68 + col + 1] = acc[mt][nt][3] * 0.0625f;
            }
    }
    __syncthreads();

    // ---- softmax per row + column-sum weights ----
    {
        const bool dk0 = dfp[lane] > 0.5f, dk1 = dfp[lane + 32] > 0.5f;
        float wa0 = 0.f, wa1 = 0.f;
#pragma unroll
        for (int r = 0; r < 8; r++) {
            int lq = w * 8 + r;
            bool dq = dfp[lq] > 0.5f;
            float s0 = sc[lq * 68 + lane], s1 = sc[lq * 68 + lane + 32];
            if (dq && dk0) s0 = -1e30f;
            if (dq && dk1) s1 = -1e30f;
            float m = fmaxf(s0, s1);
#pragma unroll
            for (int o = 16; o; o >>= 1) m = fmaxf(m, __shfl_xor_sync(0xffffffffu, m, o));
            float e0 = __expf(s0 - m), e1 = __expf(s1 - m);
            float ss = e0 + e1;
#pragma unroll
            for (int o = 16; o; o >>= 1) ss += __shfl_xor_sync(0xffffffffu, ss, o);
            float inv = 1.f / ss;
            wa0 += e0 * inv;
            wa1 += e1 * inv;
        }
        atomicAdd(&wgt[lane], wa0);
        atomicAdd(&wgt[lane + 32], wa1);
    }
    __syncthreads();

    // ---- xw[j] = sum_k wgt[k] * x[k][j] (hi+lo) ----
    {
        const __nv_bfloat16* xhp = (const __nv_bfloat16*)(smem + XH_OFF);
        const __nv_bfloat16* xlp = (const __nv_bfloat16*)(smem + XL_OFF);
        float a = 0.f;
#pragma unroll 8
        for (int k = 0; k < 64; k++)
            a += wgt[k] * (__bfloat162float(xhp[k * 264 + tid]) +
                           __bfloat162float(xlp[k * 264 + tid]));
        xw[tid] = a;
    }
    __syncthreads();

    // ---- xg[g] = bias[g] + sum_j xw[j] * W2[j][g] ----
    if (tid < 128) {
        float a = g_bias[tid];
        const float* Wp = g_W2 + tid;
#pragma unroll 4
        for (int j = 0; j < 256; j++) a += xw[j] * __ldg(Wp + (size_t)j * 128);
        g_xg[(size_t)n * 128 + tid] = a;
    }
}

// ---------------- LSTM scan + critic ----------------
__device__ __forceinline__ float sigmoidf_(float v) { return 1.f / (1.f + __expf(-v)); }

__global__ void __launch_bounds__(256) lstm_kernel(const float* __restrict__ done,
                                                   const float* __restrict__ h0,
                                                   const float* __restrict__ c0,
                                                   const float* __restrict__ whh,
                                                   const float* __restrict__ cw,
                                                   const float* __restrict__ cb,
                                                   float* __restrict__ out) {
    __shared__ float whs[32 * 128];
    const int tid = threadIdx.x, lane = tid & 31, w = tid >> 5;
    const int b = blockIdx.x * 8 + w;
    for (int idx = tid; idx < 4096; idx += 256) {
        int g = idx >> 5, m = idx & 31;
        whs[m * 128 + g] = whh[idx];
    }
    __syncthreads();
    float h = h0[b * H_DIM + lane], c = c0[b * H_DIM + lane];
    const float cwv = cw[lane], cbv = cb[0];
    for (int t = 0; t < T_STEPS; t++) {
        const int n = t * B_ENV + b;
        const float keep = 1.f - done[n];
        h *= keep; c *= keep;
        const float* xgp = g_xg + (size_t)n * 128;
        float ai = xgp[lane], af = xgp[32 + lane], ag = xgp[64 + lane], ao = xgp[96 + lane];
#pragma unroll
        for (int m = 0; m < 32; m++) {
            float hv = __shfl_sync(0xffffffffu, h, m);
            ai += hv * whs[m * 128 + lane];
            af += hv * whs[m * 128 + 32 + lane];
            ag += hv * whs[m * 128 + 64 + lane];
            ao += hv * whs[m * 128 + 96 + lane];
        }
        float gi = sigmoidf_(ai), gf = sigmoidf_(af), gg = tanhf(ag), go = sigmoidf_(ao);
        c = gf * c + gi * gg;
        h = go * tanhf(c);
        float pv = h * cwv;
#pragma unroll
        for (int o = 16; o; o >>= 1) pv += __shfl_xor_sync(0xffffffffu, pv, o);
        if (lane == 0) out[n] = pv + cbv;
    }
}

extern "C" void kernel_launch(void* const* d_in, const int* in_sizes, int n_in,
                              void* d_out, int out_size) {
    const float* x    = (const float*)d_in[0];
    const float* done = (const float*)d_in[1];
    const void*  mask = d_in[2];
    const float* h0   = (const float*)d_in[3];
    const float* c0   = (const float*)d_in[4];
    const float* ipw  = (const float*)d_in[5];
    const float* opw  = (const float*)d_in[6];
    const float* wih  = (const float*)d_in[7];
    const float* whh  = (const float*)d_in[8];
    const float* bih  = (const float*)d_in[9];
    const float* bhh  = (const float*)d_in[10];
    const float* cw   = (const float*)d_in[11];
    const float* cb   = (const float*)d_in[12];
    float*       out  = (float*)d_out;
    (void)in_sizes; (void)n_in; (void)out_size;

    cudaFuncSetAttribute(attn_mma, cudaFuncAttributeMaxDynamicSharedMemorySize, SMEM_SZ);
    expand_mask<<<(N_TOT * 64) / 256, 256>>>(mask);
    prep1<<<128, 256>>>(ipw, opw);
    prep2<<<97, 256>>>(wih, bih, bhh);
    attn_mma<<<N_TOT, 256, SMEM_SZ>>>(x);
    lstm_kernel<<<16, 256>>>(done, h0, c0, whh, cw, cb, out);
}

// round 7
// speedup vs baseline: 2.2194x; 1.6372x over previous
#include <cuda_runtime.h>
#include <cuda_bf16.h>
#include <cstdint>

#define T_STEPS 64
#define B_ENV 128
#define L_TOK 64
#define E_DIM 256
#define H_DIM 32
#define N_TOT (T_STEPS * B_ENV)

__device__ float g_M[65536];
__device__ float g_WeffT[65536];
__device__ float g_W2[32768];
__device__ float g_bias[128];
__device__ unsigned short g_MtH[65536]; // bf16 hi of M^T [j][i]
__device__ unsigned short g_MtL[65536]; // bf16 lo
__device__ float g_xg[(size_t)N_TOT * 128];
__device__ float g_df[(size_t)N_TOT * 64];

// ---------------- warp MMA helpers ----------------
__device__ __forceinline__ uint32_t smem_u32(const void* p) {
    uint32_t a;
    asm("{ .reg .u64 t; cvta.to.shared.u64 t, %1; cvt.u32.u64 %0, t; }" : "=r"(a) : "l"(p));
    return a;
}
__device__ __forceinline__ void ldm4(uint32_t* r, uint32_t a) {
    asm volatile("ldmatrix.sync.aligned.m8n8.x4.shared.b16 {%0,%1,%2,%3}, [%4];"
        : "=r"(r[0]), "=r"(r[1]), "=r"(r[2]), "=r"(r[3]) : "r"(a));
}
__device__ __forceinline__ void mma_bf16(float* d, const uint32_t* a, const uint32_t* b) {
    asm volatile("mma.sync.aligned.m16n8k16.row.col.f32.bf16.bf16.f32 "
        "{%0,%1,%2,%3}, {%4,%5,%6,%7}, {%8,%9}, {%0,%1,%2,%3};"
        : "+f"(d[0]), "+f"(d[1]), "+f"(d[2]), "+f"(d[3])
        : "r"(a[0]), "r"(a[1]), "r"(a[2]), "r"(a[3]), "r"(b[0]), "r"(b[1]));
}
__device__ __forceinline__ uint32_t pack_bf2(__nv_bfloat16 lo, __nv_bfloat16 hi) {
    __nv_bfloat162 p = __halves2bfloat162(lo, hi);
    return *(uint32_t*)&p;
}

// ---------------- mask expand (per-block dtype detect) ----------------
__global__ void __launch_bounds__(256) expand_mask(const void* __restrict__ mask) {
    __shared__ int sf, sg;
    if (!threadIdx.x) { sf = 0; sg = 0; }
    __syncthreads();
    const unsigned* w = (const unsigned*)mask;
    int f = 0, g = 0;
    for (int i = threadIdx.x; i < 2048; i += 256) {
        unsigned v = w[i];
        if (v == 0x3F800000u) f = 1;
        if (v > 1u) g = 1;
    }
    if (f) atomicOr(&sf, 1);
    if (g) atomicOr(&sg, 1);
    __syncthreads();
    int mode = sf ? 2 : (sg ? 1 : 0);
    int i = blockIdx.x * 256 + threadIdx.x;
    bool at;
    if (mode == 0)      at = ((const int*)mask)[i] != 0;
    else if (mode == 1) at = ((const uint8_t*)mask)[i] != 0;
    else                at = ((const float*)mask)[i] != 0.f;
    g_df[i] = at ? 0.f : 1.f;
}

// ---------------- prep1: M (b<64), WeffT (b>=64) ----------------
__global__ void __launch_bounds__(256) prep1(const float* __restrict__ ipw, const float* __restrict__ opw) {
    __shared__ float As[32][33], Bs[32][33];
    const int b = blockIdx.x, tid = threadIdx.x, tx = tid & 31, ty = tid >> 5;
    float acc[4] = {0.f, 0.f, 0.f, 0.f};
    if (b < 64) {
        int i0 = (b >> 3) * 32, j0 = (b & 7) * 32;
        const float *Wq = ipw, *Wk = ipw + 65536;
        for (int e0 = 0; e0 < 256; e0 += 32) {
#pragma unroll
            for (int r = 0; r < 4; r++) {
                int e = ty + 8 * r;
                As[e][tx] = Wq[(e0 + e) * 256 + i0 + tx];
                Bs[e][tx] = Wk[(e0 + e) * 256 + j0 + tx];
            }
            __syncthreads();
#pragma unroll 8
            for (int e = 0; e < 32; e++) {
                float bv = Bs[e][tx];
#pragma unroll
                for (int r = 0; r < 4; r++) acc[r] += As[e][ty + 8 * r] * bv;
            }
            __syncthreads();
        }
#pragma unroll
        for (int r = 0; r < 4; r++) g_M[(i0 + ty + 8 * r) * 256 + j0 + tx] = acc[r];
    } else {
        int t = b - 64, j0 = (t >> 3) * 32, f0 = (t & 7) * 32;
        const float* Wv = ipw + 131072;
        for (int e0 = 0; e0 < 256; e0 += 32) {
#pragma unroll
            for (int r = 0; r < 4; r++) {
                int e = ty + 8 * r;
                As[e][tx] = Wv[(e0 + e) * 256 + j0 + tx];
                Bs[tx][e] = opw[(f0 + e) * 256 + e0 + tx];
            }
            __syncthreads();
#pragma unroll 8
            for (int e = 0; e < 32; e++) {
                float bv = Bs[e][tx];
#pragma unroll
                for (int r = 0; r < 4; r++) acc[r] += As[e][ty + 8 * r] * bv;
            }
            __syncthreads();
        }
#pragma unroll
        for (int r = 0; r < 4; r++) g_WeffT[(j0 + ty + 8 * r) * 256 + f0 + tx] = acc[r];
    }
}

// ---------------- prep2: Mt split (b<64), W2 (64..95), bias (96) ----------------
__global__ void __launch_bounds__(256) prep2(const float* __restrict__ wih,
                                             const float* __restrict__ bih,
                                             const float* __restrict__ bhh) {
    __shared__ float As[32][33], Bs[32][33];
    const int b = blockIdx.x, tid = threadIdx.x, tx = tid & 31, ty = tid >> 5;
    if (b < 64) {
        int i0 = (b >> 3) * 32, j0 = (b & 7) * 32;
#pragma unroll
        for (int r = 0; r < 4; r++) As[ty + 8 * r][tx] = g_M[(i0 + ty + 8 * r) * 256 + j0 + tx];
        __syncthreads();
#pragma unroll
        for (int r = 0; r < 4; r++) {
            int jj = ty + 8 * r;
            float v = As[tx][jj];
            __nv_bfloat16 h = __float2bfloat16_rn(v);
            __nv_bfloat16 l = __float2bfloat16_rn(v - __bfloat162float(h));
            g_MtH[(j0 + jj) * 256 + i0 + tx] = *(unsigned short*)&h;
            g_MtL[(j0 + jj) * 256 + i0 + tx] = *(unsigned short*)&l;
        }
        return;
    }
    if (b < 96) {
        int t = b - 64, j0 = (t >> 2) * 32, g0 = (t & 3) * 32;
        float acc[4] = {0.f, 0.f, 0.f, 0.f};
        for (int f0 = 0; f0 < 256; f0 += 32) {
#pragma unroll
            for (int r = 0; r < 4; r++) {
                int e = ty + 8 * r;
                As[tx][e] = g_WeffT[(j0 + e) * 256 + f0 + tx];
                Bs[tx][e] = wih[(g0 + e) * 256 + f0 + tx];
            }
            __syncthreads();
#pragma unroll 8
            for (int f = 0; f < 32; f++) {
                float bv = Bs[f][tx];
#pragma unroll
                for (int r = 0; r < 4; r++) acc[r] += As[f][ty + 8 * r] * bv;
            }
            __syncthreads();
        }
#pragma unroll
        for (int r = 0; r < 4; r++) g_W2[(j0 + ty + 8 * r) * 128 + g0 + tx] = acc[r];
        return;
    }
    if (tid < 128) g_bias[tid] = bih[tid] + bhh[tid];
}

// ---------------- attention: 2 samples/CTA, 16 warps, fused chunked GEMMs ----
// x rows: 528 B (512 data + 16 pad, conflict-free ldmatrix); ts rows: 144 B.
#define ROWB 528
#define TROWB 144
#define XH_OFF   0        /* 2 x 64 x 528 = 67584 */
#define XL_OFF   67584
#define STGH_OFF 135168   /* 64 x 528 = 33792 */
#define STGL_OFF 168960
#define TSH_OFF  202752   /* 64 x 144 = 9216 */
#define TSL_OFF  211968
#define DF_OFF   221184   /* 128 f32 */
#define WGT_OFF  221696   /* 128 f32 */
#define XW_OFF   222208   /* 512 f32 */
#define SMEM_SZ  224256
#define SC_OFF   STGH_OFF /* f32 [2][64][68] overlays STG after last chunk */

__global__ void __launch_bounds__(512, 1) attn_mma(const float* __restrict__ x) {
    extern __shared__ char smem[];
    const uint32_t sb = smem_u32(smem);
    const int tid = threadIdx.x, lane = tid & 31, w = tid >> 5;
    const int n0 = blockIdx.x * 2;
    float* dfp = (float*)(smem + DF_OFF);
    float* wgt = (float*)(smem + WGT_OFF);
    float* xw  = (float*)(smem + XW_OFF);

    // load x (2 samples) f32 -> bf16 hi/lo smem
    const float2* xb = (const float2*)(x + (size_t)n0 * (L_TOK * E_DIM));
    for (int idx = tid; idx < 16384; idx += 512) {
        int s = idx >> 13, r = (idx >> 7) & 63, cp = idx & 127;
        float2 v = xb[idx];
        __nv_bfloat16 h0 = __float2bfloat16_rn(v.x), h1 = __float2bfloat16_rn(v.y);
        __nv_bfloat16 l0 = __float2bfloat16_rn(v.x - __bfloat162float(h0));
        __nv_bfloat16 l1 = __float2bfloat16_rn(v.y - __bfloat162float(h1));
        uint32_t boff = (uint32_t)(s * 33792 + r * ROWB + cp * 4);
        *(uint32_t*)(smem + XH_OFF + boff) = pack_bf2(h0, h1);
        *(uint32_t*)(smem + XL_OFF + boff) = pack_bf2(l0, l1);
    }
    if (tid < 128) { dfp[tid] = g_df[(size_t)n0 * 64 + tid]; wgt[tid] = 0.f; }

    // warp tile: 16x16 of the 64x64 outputs
    const int mg = w >> 2, ng = w & 3;
    const uint32_t a_off  = (uint32_t)((mg * 16 + (lane & 15)) * ROWB + ((lane >> 4) << 4));
    const uint32_t at_off = (uint32_t)((mg * 16 + (lane & 15)) * TROWB + ((lane >> 4) << 4));
    const int brow = ng * 16 + (lane & 7) + ((lane & 16) >> 1);
    const uint32_t bc16 = (uint32_t)(((lane >> 3) & 1) << 4);

    float acc2[2][2][4];
#pragma unroll
    for (int s = 0; s < 2; s++)
#pragma unroll
        for (int nt = 0; nt < 2; nt++)
#pragma unroll
            for (int q = 0; q < 4; q++) acc2[s][nt][q] = 0.f;

    for (int ch = 0; ch < 4; ch++) {
        // stage Mt chunk (hi + lo): rows ch*64..+64, all 256 i
        {
            const uint32_t* sh = (const uint32_t*)g_MtH + ch * 8192;
            const uint32_t* sl = (const uint32_t*)g_MtL + ch * 8192;
            for (int u = tid; u < 8192; u += 512) {
                uint32_t d = (uint32_t)((u >> 7) * ROWB + (u & 127) * 4);
                *(uint32_t*)(smem + STGH_OFF + d) = sh[u];
                *(uint32_t*)(smem + STGL_OFF + d) = sl[u];
            }
        }
        __syncthreads();

#pragma unroll 1
        for (int s = 0; s < 2; s++) {
            // GEMM1 chunk: ts_ch[64][64] = x_s @ Mt_ch^T (3 terms, K=256)
            float acc1[2][4];
#pragma unroll
            for (int nt = 0; nt < 2; nt++)
#pragma unroll
                for (int q = 0; q < 4; q++) acc1[nt][q] = 0.f;
            const uint32_t axh = sb + XH_OFF + s * 33792 + a_off;
            const uint32_t axl = sb + XL_OFF + s * 33792 + a_off;
            const uint32_t bmh = sb + STGH_OFF + brow * ROWB + bc16;
            const uint32_t bml = sb + STGL_OFF + brow * ROWB + bc16;
#pragma unroll 4
            for (int ks = 0; ks < 16; ks++) {
                uint32_t kb = ks * 32;
                uint32_t Ah[4], Al[4], Bh[4], Bl[4];
                ldm4(Ah, axh + kb);
                ldm4(Al, axl + kb);
                ldm4(Bh, bmh + kb);
                ldm4(Bl, bml + kb);
                mma_bf16(acc1[0], Ah, Bh); mma_bf16(acc1[1], Ah, Bh + 2);
                mma_bf16(acc1[0], Al, Bh); mma_bf16(acc1[1], Al, Bh + 2);
                mma_bf16(acc1[0], Ah, Bl); mma_bf16(acc1[1], Ah, Bl + 2);
            }
            if (s == 1) __syncthreads();  // protect ts from sample-0 GEMM2 readers
            // write ts chunk as bf16 hi/lo
#pragma unroll
            for (int nt = 0; nt < 2; nt++) {
                int col = ng * 16 + nt * 8 + 2 * (lane & 3);
                int r0 = mg * 16 + (lane >> 2);
#pragma unroll
                for (int hh = 0; hh < 2; hh++) {
                    float v0 = acc1[nt][2 * hh], v1 = acc1[nt][2 * hh + 1];
                    __nv_bfloat16 h0 = __float2bfloat16_rn(v0), h1 = __float2bfloat16_rn(v1);
                    __nv_bfloat16 l0 = __float2bfloat16_rn(v0 - __bfloat162float(h0));
                    __nv_bfloat16 l1 = __float2bfloat16_rn(v1 - __bfloat162float(h1));
                    uint32_t boff = (uint32_t)((r0 + 8 * hh) * TROWB + col * 2);
                    *(uint32_t*)(smem + TSH_OFF + boff) = pack_bf2(h0, h1);
                    *(uint32_t*)(smem + TSL_OFF + boff) = pack_bf2(l0, l1);
                }
            }
            __syncthreads();
            // GEMM2 partial: sc_s += ts_ch @ x_ch^T (3 terms, K=64)
            const uint32_t ath = sb + TSH_OFF + at_off;
            const uint32_t atl = sb + TSL_OFF + at_off;
            const uint32_t bxh = sb + XH_OFF + s * 33792 + brow * ROWB + ch * 128 + bc16;
            const uint32_t bxl = sb + XL_OFF + s * 33792 + brow * ROWB + ch * 128 + bc16;
#pragma unroll
            for (int ks = 0; ks < 4; ks++) {
                uint32_t kb = ks * 32;
                uint32_t Ah[4], Al[4], Bh[4], Bl[4];
                ldm4(Ah, ath + kb);
                ldm4(Al, atl + kb);
                ldm4(Bh, bxh + kb);
                ldm4(Bl, bxl + kb);
                mma_bf16(acc2[s][0], Ah, Bh); mma_bf16(acc2[s][1], Ah, Bh + 2);
                mma_bf16(acc2[s][0], Al, Bh); mma_bf16(acc2[s][1], Al, Bh + 2);
                mma_bf16(acc2[s][0], Ah, Bl); mma_bf16(acc2[s][1], Ah, Bl + 2);
            }
        }
        __syncthreads();  // all GEMM2 done before restaging STG (next chunk) / SC overlay
    }

    // ---- write sc (overlay STG), scaled ----
    {
#pragma unroll
        for (int s = 0; s < 2; s++) {
            float* scp = (float*)(smem + SC_OFF) + s * 4352;
#pragma unroll
            for (int nt = 0; nt < 2; nt++) {
                int col = ng * 16 + nt * 8 + 2 * (lane & 3);
                int r0 = mg * 16 + (lane >> 2);
                scp[r0 * 68 + col]           = acc2[s][nt][0] * 0.0625f;
                scp[r0 * 68 + col + 1]       = acc2[s][nt][1] * 0.0625f;
                scp[(r0 + 8) * 68 + col]     = acc2[s][nt][2] * 0.0625f;
                scp[(r0 + 8) * 68 + col + 1] = acc2[s][nt][3] * 0.0625f;
            }
        }
    }
    __syncthreads();

    // ---- softmax: warps 0-7 -> sample 0, 8-15 -> sample 1; 8 rows/warp ----
    {
        const int s = w >> 3, w8 = w & 7;
        const float* scp = (const float*)(smem + SC_OFF) + s * 4352;
        const float* dfs = dfp + s * 64;
        const bool dk0 = dfs[lane] > 0.5f, dk1 = dfs[lane + 32] > 0.5f;
        float wa0 = 0.f, wa1 = 0.f;
#pragma unroll
        for (int r = 0; r < 8; r++) {
            int lq = w8 * 8 + r;
            bool dq = dfs[lq] > 0.5f;
            float s0 = scp[lq * 68 + lane], s1 = scp[lq * 68 + lane + 32];
            if (dq && dk0) s0 = -1e30f;
            if (dq && dk1) s1 = -1e30f;
            float m = fmaxf(s0, s1);
#pragma unroll
            for (int o = 16; o; o >>= 1) m = fmaxf(m, __shfl_xor_sync(0xffffffffu, m, o));
            float e0 = __expf(s0 - m), e1 = __expf(s1 - m);
            float ss = e0 + e1;
#pragma unroll
            for (int o = 16; o; o >>= 1) ss += __shfl_xor_sync(0xffffffffu, ss, o);
            float inv = 1.f / ss;
            wa0 += e0 * inv;
            wa1 += e1 * inv;
        }
        atomicAdd(&wgt[s * 64 + lane], wa0);
        atomicAdd(&wgt[s * 64 + lane + 32], wa1);
    }
    __syncthreads();

    // ---- xw[s][j] = sum_k wgt[s][k] * x[s][k][j] (hi+lo) ----
    {
        const int s = tid >> 8, j = tid & 255;
        float a = 0.f;
#pragma unroll 8
        for (int k = 0; k < 64; k++) {
            uint32_t boff = (uint32_t)(s * 33792 + k * ROWB + j * 2);
            a += wgt[s * 64 + k] *
                 (__bfloat162float(*(__nv_bfloat16*)(smem + XH_OFF + boff)) +
                  __bfloat162float(*(__nv_bfloat16*)(smem + XL_OFF + boff)));
        }
        xw[tid] = a;
    }
    __syncthreads();

    // ---- xg[s][g] = bias[g] + sum_j xw[s][j] * W2[j][g] ----
    if (tid < 256) {
        const int s = tid >> 7, g = tid & 127;
        float a = g_bias[g];
        const float* xwp = xw + s * 256;
        const float* Wp = g_W2 + g;
#pragma unroll 4
        for (int j = 0; j < 256; j++) a += xwp[j] * __ldg(Wp + (size_t)j * 128);
        g_xg[(size_t)(n0 + s) * 128 + g] = a;
    }
}

// ---------------- LSTM scan + critic ----------------
__device__ __forceinline__ float sigmoidf_(float v) { return 1.f / (1.f + __expf(-v)); }

__global__ void __launch_bounds__(256) lstm_kernel(const float* __restrict__ done,
                                                   const float* __restrict__ h0,
                                                   const float* __restrict__ c0,
                                                   const float* __restrict__ whh,
                                                   const float* __restrict__ cw,
                                                   const float* __restrict__ cb,
                                                   float* __restrict__ out) {
    __shared__ float whs[32 * 128];
    const int tid = threadIdx.x, lane = tid & 31, w = tid >> 5;
    const int b = blockIdx.x * 8 + w;
    for (int idx = tid; idx < 4096; idx += 256) {
        int g = idx >> 5, m = idx & 31;
        whs[m * 128 + g] = whh[idx];
    }
    __syncthreads();
    float h = h0[b * H_DIM + lane], c = c0[b * H_DIM + lane];
    const float cwv = cw[lane], cbv = cb[0];
    for (int t = 0; t < T_STEPS; t++) {
        const int n = t * B_ENV + b;
        const float keep = 1.f - done[n];
        h *= keep; c *= keep;
        const float* xgp = g_xg + (size_t)n * 128;
        float ai = xgp[lane], af = xgp[32 + lane], ag = xgp[64 + lane], ao = xgp[96 + lane];
#pragma unroll
        for (int m = 0; m < 32; m++) {
            float hv = __shfl_sync(0xffffffffu, h, m);
            ai += hv * whs[m * 128 + lane];
            af += hv * whs[m * 128 + 32 + lane];
            ag += hv * whs[m * 128 + 64 + lane];
            ao += hv * whs[m * 128 + 96 + lane];
        }
        float gi = sigmoidf_(ai), gf = sigmoidf_(af), gg = tanhf(ag), go = sigmoidf_(ao);
        c = gf * c + gi * gg;
        h = go * tanhf(c);
        float pv = h * cwv;
#pragma unroll
        for (int o = 16; o; o >>= 1) pv += __shfl_xor_sync(0xffffffffu, pv, o);
        if (lane == 0) out[n] = pv + cbv;
    }
}

extern "C" void kernel_launch(void* const* d_in, const int* in_sizes, int n_in,
                              void* d_out, int out_size) {
    const float* x    = (const float*)d_in[0];
    const float* done = (const float*)d_in[1];
    const void*  mask = d_in[2];
    const float* h0   = (const float*)d_in[3];
    const float* c0   = (const float*)d_in[4];
    const float* ipw  = (const float*)d_in[5];
    const float* opw  = (const float*)d_in[6];
    const float* wih  = (const float*)d_in[7];
    const float* whh  = (const float*)d_in[8];
    const float* bih  = (const float*)d_in[9];
    const float* bhh  = (const float*)d_in[10];
    const float* cw   = (const float*)d_in[11];
    const float* cb   = (const float*)d_in[12];
    float*       out  = (float*)d_out;
    (void)in_sizes; (void)n_in; (void)out_size;

    cudaFuncSetAttribute(attn_mma, cudaFuncAttributeMaxDynamicSharedMemorySize, SMEM_SZ);
    expand_mask<<<(N_TOT * 64) / 256, 256>>>(mask);
    prep1<<<128, 256>>>(ipw, opw);
    prep2<<<97, 256>>>(wih, bih, bhh);
    attn_mma<<<N_TOT / 2, 512, SMEM_SZ>>>(x);
    lstm_kernel<<<16, 256>>>(done, h0, c0, whh, cw, cb, out);
}

// round 8
// speedup vs baseline: 2.6281x; 1.1841x over previous
#include <cuda_runtime.h>
#include <cuda_bf16.h>
#include <cstdint>

#define T_STEPS 64
#define B_ENV 128
#define L_TOK 64
#define E_DIM 256
#define H_DIM 32
#define N_TOT (T_STEPS * B_ENV)

__device__ float g_M[65536];
__device__ float g_WeffT[65536];
__device__ float g_W2[32768];
__device__ float g_bias[128];
__device__ unsigned short g_MtH[65536]; // bf16 hi of M^T [j][i]
__device__ unsigned short g_MtL[65536]; // bf16 lo
__device__ float g_xg[(size_t)N_TOT * 128];

// ---------------- helpers ----------------
__device__ __forceinline__ uint32_t smem_u32(const void* p) {
    uint32_t a;
    asm("{ .reg .u64 t; cvta.to.shared.u64 t, %1; cvt.u32.u64 %0, t; }" : "=r"(a) : "l"(p));
    return a;
}
__device__ __forceinline__ void ldm4(uint32_t* r, uint32_t a) {
    asm volatile("ldmatrix.sync.aligned.m8n8.x4.shared.b16 {%0,%1,%2,%3}, [%4];"
        : "=r"(r[0]), "=r"(r[1]), "=r"(r[2]), "=r"(r[3]) : "r"(a));
}
__device__ __forceinline__ void mma_bf16(float* d, const uint32_t* a, const uint32_t* b) {
    asm volatile("mma.sync.aligned.m16n8k16.row.col.f32.bf16.bf16.f32 "
        "{%0,%1,%2,%3}, {%4,%5,%6,%7}, {%8,%9}, {%0,%1,%2,%3};"
        : "+f"(d[0]), "+f"(d[1]), "+f"(d[2]), "+f"(d[3])
        : "r"(a[0]), "r"(a[1]), "r"(a[2]), "r"(a[3]), "r"(b[0]), "r"(b[1]));
}
__device__ __forceinline__ uint32_t pack_bf2(__nv_bfloat16 lo, __nv_bfloat16 hi) {
    __nv_bfloat162 p = __halves2bfloat162(lo, hi);
    return *(uint32_t*)&p;
}
__device__ __forceinline__ void cp16(uint32_t dst, const void* src) {
    asm volatile("cp.async.cg.shared.global [%0], [%1], 16;" :: "r"(dst), "l"(src));
}
#define CP_COMMIT() asm volatile("cp.async.commit_group;" ::: "memory")
#define CP_WAIT0()  asm volatile("cp.async.wait_group 0;" ::: "memory")

// ---------------- prep1: M (b<64), WeffT (b>=64) ----------------
__global__ void __launch_bounds__(256) prep1(const float* __restrict__ ipw, const float* __restrict__ opw) {
    __shared__ float As[32][33], Bs[32][33];
    const int b = blockIdx.x, tid = threadIdx.x, tx = tid & 31, ty = tid >> 5;
    float acc[4] = {0.f, 0.f, 0.f, 0.f};
    if (b < 64) {
        int i0 = (b >> 3) * 32, j0 = (b & 7) * 32;
        const float *Wq = ipw, *Wk = ipw + 65536;
        for (int e0 = 0; e0 < 256; e0 += 32) {
#pragma unroll
            for (int r = 0; r < 4; r++) {
                int e = ty + 8 * r;
                As[e][tx] = Wq[(e0 + e) * 256 + i0 + tx];
                Bs[e][tx] = Wk[(e0 + e) * 256 + j0 + tx];
            }
            __syncthreads();
#pragma unroll 8
            for (int e = 0; e < 32; e++) {
                float bv = Bs[e][tx];
#pragma unroll
                for (int r = 0; r < 4; r++) acc[r] += As[e][ty + 8 * r] * bv;
            }
            __syncthreads();
        }
#pragma unroll
        for (int r = 0; r < 4; r++) g_M[(i0 + ty + 8 * r) * 256 + j0 + tx] = acc[r];
    } else {
        int t = b - 64, j0 = (t >> 3) * 32, f0 = (t & 7) * 32;
        const float* Wv = ipw + 131072;
        for (int e0 = 0; e0 < 256; e0 += 32) {
#pragma unroll
            for (int r = 0; r < 4; r++) {
                int e = ty + 8 * r;
                As[e][tx] = Wv[(e0 + e) * 256 + j0 + tx];
                Bs[tx][e] = opw[(f0 + e) * 256 + e0 + tx];
            }
            __syncthreads();
#pragma unroll 8
            for (int e = 0; e < 32; e++) {
                float bv = Bs[e][tx];
#pragma unroll
                for (int r = 0; r < 4; r++) acc[r] += As[e][ty + 8 * r] * bv;
            }
            __syncthreads();
        }
#pragma unroll
        for (int r = 0; r < 4; r++) g_WeffT[(j0 + ty + 8 * r) * 256 + f0 + tx] = acc[r];
    }
}

// ---------------- prep2: Mt split (b<64), W2 (64..95), bias (96) ----------------
__global__ void __launch_bounds__(256) prep2(const float* __restrict__ wih,
                                             const float* __restrict__ bih,
                                             const float* __restrict__ bhh) {
    __shared__ float As[32][33], Bs[32][33];
    const int b = blockIdx.x, tid = threadIdx.x, tx = tid & 31, ty = tid >> 5;
    if (b < 64) {
        int i0 = (b >> 3) * 32, j0 = (b & 7) * 32;
#pragma unroll
        for (int r = 0; r < 4; r++) As[ty + 8 * r][tx] = g_M[(i0 + ty + 8 * r) * 256 + j0 + tx];
        __syncthreads();
#pragma unroll
        for (int r = 0; r < 4; r++) {
            int jj = ty + 8 * r;
            float v = As[tx][jj];
            __nv_bfloat16 h = __float2bfloat16_rn(v);
            __nv_bfloat16 l = __float2bfloat16_rn(v - __bfloat162float(h));
            g_MtH[(j0 + jj) * 256 + i0 + tx] = *(unsigned short*)&h;
            g_MtL[(j0 + jj) * 256 + i0 + tx] = *(unsigned short*)&l;
        }
        return;
    }
    if (b < 96) {
        int t = b - 64, j0 = (t >> 2) * 32, g0 = (t & 3) * 32;
        float acc[4] = {0.f, 0.f, 0.f, 0.f};
        for (int f0 = 0; f0 < 256; f0 += 32) {
#pragma unroll
            for (int r = 0; r < 4; r++) {
                int e = ty + 8 * r;
                As[tx][e] = g_WeffT[(j0 + e) * 256 + f0 + tx];
                Bs[tx][e] = wih[(g0 + e) * 256 + f0 + tx];
            }
            __syncthreads();
#pragma unroll 8
            for (int f = 0; f < 32; f++) {
                float bv = Bs[f][tx];
#pragma unroll
                for (int r = 0; r < 4; r++) acc[r] += As[f][ty + 8 * r] * bv;
            }
            __syncthreads();
        }
#pragma unroll
        for (int r = 0; r < 4; r++) g_W2[(j0 + ty + 8 * r) * 128 + g0 + tx] = acc[r];
        return;
    }
    if (tid < 128) g_bias[tid] = bih[tid] + bhh[tid];
}

// ---------------- attention ----------------
// x/STG rows: 512 B, XOR swizzle ((row&7)<<4); ts rows: 128 B, same swizzle.
#define XH_OFF   0        /* 2 x 64 x 512 */
#define XL_OFF   65536
#define STGH_OFF 131072   /* 64 x 512 */
#define STGL_OFF 163840
#define TSH_OFF  196608   /* 2 x 64 x 128 */
#define TSL_OFF  212992
#define SMEM_SZ  229376
#define SC_OFF   STGH_OFF          /* f32 [2][64][68] after GEMMs */
#define DF_OFF   TSH_OFF           /* overlays ts after GEMMs */
#define WGT_OFF  (TSH_OFF + 512)
#define XW_OFF   (TSH_OFF + 1024)
#define MODE_OFF (TSH_OFF + 3072)

__global__ void __launch_bounds__(512, 1) attn_mma(const float* __restrict__ x,
                                                   const void* __restrict__ mask) {
    extern __shared__ char smem[];
    const uint32_t sb = smem_u32(smem);
    const int tid = threadIdx.x, lane = tid & 31, w = tid >> 5;
    const int n0 = blockIdx.x * 2;

    // stage chunk 0 of Mt (hi+lo) via cp.async
    {
        for (int u = tid; u < 4096; u += 512) {
            int buf = u >> 11, v = u & 2047;
            int row = v >> 5, c16 = (v & 31) << 4;
            uint32_t d = (buf ? STGL_OFF : STGH_OFF) + row * 512 + (c16 ^ ((row & 7) << 4));
            const uint4* s = (const uint4*)(buf ? g_MtL : g_MtH) + v;
            cp16(sb + d, s);
        }
        CP_COMMIT();
    }

    // load x (2 samples) f32 -> bf16 hi/lo smem (swizzled)
    const float2* xb = (const float2*)(x + (size_t)n0 * (L_TOK * E_DIM));
    for (int idx = tid; idx < 16384; idx += 512) {
        int s = idx >> 13, r = (idx >> 7) & 63, cp = idx & 127;
        float2 v = xb[idx];
        __nv_bfloat16 h0 = __float2bfloat16_rn(v.x), h1 = __float2bfloat16_rn(v.y);
        __nv_bfloat16 l0 = __float2bfloat16_rn(v.x - __bfloat162float(h0));
        __nv_bfloat16 l1 = __float2bfloat16_rn(v.y - __bfloat162float(h1));
        uint32_t boff = (uint32_t)(s * 32768 + r * 512 + ((cp * 4) ^ ((r & 7) << 4)));
        *(uint32_t*)(smem + XH_OFF + boff) = pack_bf2(h0, h1);
        *(uint32_t*)(smem + XL_OFF + boff) = pack_bf2(l0, l1);
    }
    CP_WAIT0();
    __syncthreads();

    // warp layout: s = w>>3 (sample), tile m16 x n32
    const int s = w >> 3, w8 = w & 7, mg = w8 >> 1, ng = w8 & 1;
    const int arow = mg * 16 + (lane & 15);
    const uint32_t a_rot = (arow & 7) << 4, a_klo = (lane >> 4) << 4;
    const uint32_t axh = sb + XH_OFF + s * 32768 + arow * 512;
    const uint32_t axl = sb + XL_OFF + s * 32768 + arow * 512;
    const uint32_t ath = sb + TSH_OFF + s * 8192 + arow * 128;
    const uint32_t atl = sb + TSL_OFF + s * 8192 + arow * 128;
    const int br0 = ng * 32 + (lane & 7) + ((lane & 16) >> 1), br1 = br0 + 16;
    const uint32_t b_rot0 = (br0 & 7) << 4, b_rot1 = (br1 & 7) << 4;
    const uint32_t bklo = ((lane >> 3) & 1) << 4;

    float acc2[4][4];
#pragma unroll
    for (int nt = 0; nt < 4; nt++)
#pragma unroll
        for (int q = 0; q < 4; q++) acc2[nt][q] = 0.f;

    for (int ch = 0; ch < 4; ch++) {
        // GEMM1 chunk: ts_ch[64][64] = x_s @ Mt_ch^T (3 terms, K=256)
        float acc1[4][4];
#pragma unroll
        for (int nt = 0; nt < 4; nt++)
#pragma unroll
            for (int q = 0; q < 4; q++) acc1[nt][q] = 0.f;
        const uint32_t sgh0 = sb + STGH_OFF + br0 * 512, sgh1 = sb + STGH_OFF + br1 * 512;
        const uint32_t sgl0 = sb + STGL_OFF + br0 * 512, sgl1 = sb + STGL_OFF + br1 * 512;
#pragma unroll 4
        for (int ks = 0; ks < 16; ks++) {
            uint32_t kb = ks * 32;
            uint32_t Ah[4], Al[4], Bh0[4], Bh1[4], Bl0[4], Bl1[4];
            ldm4(Ah, axh + ((kb + a_klo) ^ a_rot));
            ldm4(Al, axl + ((kb + a_klo) ^ a_rot));
            ldm4(Bh0, sgh0 + ((kb + bklo) ^ b_rot0));
            ldm4(Bh1, sgh1 + ((kb + bklo) ^ b_rot1));
            ldm4(Bl0, sgl0 + ((kb + bklo) ^ b_rot0));
            ldm4(Bl1, sgl1 + ((kb + bklo) ^ b_rot1));
            mma_bf16(acc1[0], Ah, Bh0); mma_bf16(acc1[1], Ah, Bh0 + 2);
            mma_bf16(acc1[2], Ah, Bh1); mma_bf16(acc1[3], Ah, Bh1 + 2);
            mma_bf16(acc1[0], Al, Bh0); mma_bf16(acc1[1], Al, Bh0 + 2);
            mma_bf16(acc1[2], Al, Bh1); mma_bf16(acc1[3], Al, Bh1 + 2);
            mma_bf16(acc1[0], Ah, Bl0); mma_bf16(acc1[1], Ah, Bl0 + 2);
            mma_bf16(acc1[2], Ah, Bl1); mma_bf16(acc1[3], Ah, Bl1 + 2);
        }
        // write ts chunk (bf16 hi/lo, swizzled 128B rows)
#pragma unroll
        for (int nt = 0; nt < 4; nt++) {
            int col = ng * 32 + nt * 8 + 2 * (lane & 3);
            int r0 = mg * 16 + (lane >> 2);
#pragma unroll
            for (int hh = 0; hh < 2; hh++) {
                int rr = r0 + 8 * hh;
                float v0 = acc1[nt][2 * hh], v1 = acc1[nt][2 * hh + 1];
                __nv_bfloat16 h0 = __float2bfloat16_rn(v0), h1 = __float2bfloat16_rn(v1);
                __nv_bfloat16 l0 = __float2bfloat16_rn(v0 - __bfloat162float(h0));
                __nv_bfloat16 l1 = __float2bfloat16_rn(v1 - __bfloat162float(h1));
                uint32_t boff = (uint32_t)(s * 8192 + rr * 128 + ((col * 2) ^ ((rr & 7) << 4)));
                *(uint32_t*)(smem + TSH_OFF + boff) = pack_bf2(h0, h1);
                *(uint32_t*)(smem + TSL_OFF + boff) = pack_bf2(l0, l1);
            }
        }
        __syncthreads();   // ts visible; GEMM1 done reading STG

        // prefetch next Mt chunk (overlaps GEMM2)
        if (ch < 3) {
            for (int u = tid; u < 4096; u += 512) {
                int buf = u >> 11, v = u & 2047;
                int row = v >> 5, c16 = (v & 31) << 4;
                uint32_t d = (buf ? STGL_OFF : STGH_OFF) + row * 512 + (c16 ^ ((row & 7) << 4));
                const uint4* sp = (const uint4*)((buf ? g_MtL : g_MtH) + (ch + 1) * 16384) + v;
                cp16(sb + d, sp);
            }
            CP_COMMIT();
        }

        // GEMM2 partial: sc_s += ts_ch @ x_ch^T (3 terms, K=64)
        const uint32_t bxh0 = sb + XH_OFF + s * 32768 + br0 * 512;
        const uint32_t bxh1 = sb + XH_OFF + s * 32768 + br1 * 512;
        const uint32_t bxl0 = sb + XL_OFF + s * 32768 + br0 * 512;
        const uint32_t bxl1 = sb + XL_OFF + s * 32768 + br1 * 512;
#pragma unroll
        for (int ks = 0; ks < 4; ks++) {
            uint32_t kb = ks * 32, xc = ch * 128 + kb + bklo;
            uint32_t Ah[4], Al[4], Bh0[4], Bh1[4], Bl0[4], Bl1[4];
            ldm4(Ah, ath + ((kb + a_klo) ^ a_rot));
            ldm4(Al, atl + ((kb + a_klo) ^ a_rot));
            ldm4(Bh0, bxh0 + (xc ^ b_rot0));
            ldm4(Bh1, bxh1 + (xc ^ b_rot1));
            ldm4(Bl0, bxl0 + (xc ^ b_rot0));
            ldm4(Bl1, bxl1 + (xc ^ b_rot1));
            mma_bf16(acc2[0], Ah, Bh0); mma_bf16(acc2[1], Ah, Bh0 + 2);
            mma_bf16(acc2[2], Ah, Bh1); mma_bf16(acc2[3], Ah, Bh1 + 2);
            mma_bf16(acc2[0], Al, Bh0); mma_bf16(acc2[1], Al, Bh0 + 2);
            mma_bf16(acc2[2], Al, Bh1); mma_bf16(acc2[3], Al, Bh1 + 2);
            mma_bf16(acc2[0], Ah, Bl0); mma_bf16(acc2[1], Ah, Bl0 + 2);
            mma_bf16(acc2[2], Ah, Bl1); mma_bf16(acc2[3], Ah, Bl1 + 2);
        }
        if (ch < 3) { CP_WAIT0(); }
        __syncthreads();   // next GEMM1 may read STG; ts rewrite safe
    }

    // ---- write sc (overlay STG), scaled; warp 0 detects mask dtype ----
    float* scp = (float*)(smem + SC_OFF) + s * 4352;
#pragma unroll
    for (int nt = 0; nt < 4; nt++) {
        int col = ng * 32 + nt * 8 + 2 * (lane & 3);
        int r0 = mg * 16 + (lane >> 2);
        scp[r0 * 68 + col]           = acc2[nt][0] * 0.0625f;
        scp[r0 * 68 + col + 1]       = acc2[nt][1] * 0.0625f;
        scp[(r0 + 8) * 68 + col]     = acc2[nt][2] * 0.0625f;
        scp[(r0 + 8) * 68 + col + 1] = acc2[nt][3] * 0.0625f;
    }
    if (w == 0) {
        const unsigned* mw = (const unsigned*)mask;
        int f = 0, g = 0;
        for (int i = lane; i < 2048; i += 32) {
            unsigned v = mw[i];
            f |= (v == 0x3F800000u);
            g |= (v > 1u);
        }
        f = __any_sync(0xffffffffu, f);
        g = __any_sync(0xffffffffu, g);
        if (!lane) *(int*)(smem + MODE_OFF) = f ? 2 : (g ? 1 : 0);
    }
    __syncthreads();

    // ---- dropped flags + wgt init ----
    float* dfp = (float*)(smem + DF_OFF);
    float* wgt = (float*)(smem + WGT_OFF);
    float* xw  = (float*)(smem + XW_OFF);
    if (tid < 128) {
        int mode = *(int*)(smem + MODE_OFF);
        size_t mi = (size_t)n0 * 64 + tid;
        bool at;
        if (mode == 0)      at = ((const int*)mask)[mi] != 0;
        else if (mode == 1) at = ((const uint8_t*)mask)[mi] != 0;
        else                at = ((const float*)mask)[mi] != 0.f;
        dfp[tid] = at ? 0.f : 1.f;
        wgt[tid] = 0.f;
    }
    __syncthreads();

    // ---- softmax: 8 rows/warp ----
    {
        const int w8s = w & 7;
        const float* scs = (const float*)(smem + SC_OFF) + s * 4352;
        const float* dfs = dfp + s * 64;
        const bool dk0 = dfs[lane] > 0.5f, dk1 = dfs[lane + 32] > 0.5f;
        float wa0 = 0.f, wa1 = 0.f;
#pragma unroll
        for (int r = 0; r < 8; r++) {
            int lq = w8s * 8 + r;
            bool dq = dfs[lq] > 0.5f;
            float s0 = scs[lq * 68 + lane], s1 = scs[lq * 68 + lane + 32];
            if (dq && dk0) s0 = -1e30f;
            if (dq && dk1) s1 = -1e30f;
            float m = fmaxf(s0, s1);
#pragma unroll
            for (int o = 16; o; o >>= 1) m = fmaxf(m, __shfl_xor_sync(0xffffffffu, m, o));
            float e0 = __expf(s0 - m), e1 = __expf(s1 - m);
            float ss = e0 + e1;
#pragma unroll
            for (int o = 16; o; o >>= 1) ss += __shfl_xor_sync(0xffffffffu, ss, o);
            float inv = 1.f / ss;
            wa0 += e0 * inv;
            wa1 += e1 * inv;
        }
        atomicAdd(&wgt[s * 64 + lane], wa0);
        atomicAdd(&wgt[s * 64 + lane + 32], wa1);
    }
    __syncthreads();

    // ---- xw[s][j] = sum_k wgt[s][k] * x[s][k][j] (hi+lo, swizzled) ----
    {
        const int ss = tid >> 8, j = tid & 255;
        float a = 0.f;
#pragma unroll 8
        for (int k = 0; k < 64; k++) {
            uint32_t boff = (uint32_t)(ss * 32768 + k * 512 + ((2 * j) ^ ((k & 7) << 4)));
            a += wgt[ss * 64 + k] *
                 (__bfloat162float(*(__nv_bfloat16*)(smem + XH_OFF + boff)) +
                  __bfloat162float(*(__nv_bfloat16*)(smem + XL_OFF + boff)));
        }
        xw[tid] = a;
    }
    __syncthreads();

    // ---- xg[s][g] = bias[g] + sum_j xw[s][j] * W2[j][g] ----
    if (tid < 256) {
        const int ss = tid >> 7, g = tid & 127;
        float a = g_bias[g];
        const float* xwp = xw + ss * 256;
        const float* Wp = g_W2 + g;
#pragma unroll 4
        for (int j = 0; j < 256; j++) a += xwp[j] * __ldg(Wp + (size_t)j * 128);
        g_xg[(size_t)(n0 + ss) * 128 + g] = a;
    }
}

// ---------------- LSTM scan + critic ----------------
__device__ __forceinline__ float sigmoidf_(float v) { return 1.f / (1.f + __expf(-v)); }

__global__ void __launch_bounds__(256) lstm_kernel(const float* __restrict__ done,
                                                   const float* __restrict__ h0,
                                                   const float* __restrict__ c0,
                                                   const float* __restrict__ whh,
                                                   const float* __restrict__ cw,
                                                   const float* __restrict__ cb,
                                                   float* __restrict__ out) {
    __shared__ float whs[32 * 128];
    const int tid = threadIdx.x, lane = tid & 31, w = tid >> 5;
    const int b = blockIdx.x * 8 + w;
    for (int idx = tid; idx < 4096; idx += 256) {
        int g = idx >> 5, m = idx & 31;
        whs[m * 128 + g] = whh[idx];
    }
    __syncthreads();
    float h = h0[b * H_DIM + lane], c = c0[b * H_DIM + lane];
    const float cwv = cw[lane], cbv = cb[0];
    for (int t = 0; t < T_STEPS; t++) {
        const int n = t * B_ENV + b;
        const float keep = 1.f - done[n];
        h *= keep; c *= keep;
        const float* xgp = g_xg + (size_t)n * 128;
        float ai = xgp[lane], af = xgp[32 + lane], ag = xgp[64 + lane], ao = xgp[96 + lane];
#pragma unroll
        for (int m = 0; m < 32; m++) {
            float hv = __shfl_sync(0xffffffffu, h, m);
            ai += hv * whs[m * 128 + lane];
            af += hv * whs[m * 128 + 32 + lane];
            ag += hv * whs[m * 128 + 64 + lane];
            ao += hv * whs[m * 128 + 96 + lane];
        }
        float gi = sigmoidf_(ai), gf = sigmoidf_(af), gg = tanhf(ag), go = sigmoidf_(ao);
        c = gf * c + gi * gg;
        h = go * tanhf(c);
        float pv = h * cwv;
#pragma unroll
        for (int o = 16; o; o >>= 1) pv += __shfl_xor_sync(0xffffffffu, pv, o);
        if (lane == 0) out[n] = pv + cbv;
    }
}

extern "C" void kernel_launch(void* const* d_in, const int* in_sizes, int n_in,
                              void* d_out, int out_size) {
    const float* x    = (const float*)d_in[0];
    const float* done = (const float*)d_in[1];
    const void*  mask = d_in[2];
    const float* h0   = (const float*)d_in[3];
    const float* c0   = (const float*)d_in[4];
    const float* ipw  = (const float*)d_in[5];
    const float* opw  = (const float*)d_in[6];
    const float* wih  = (const float*)d_in[7];
    const float* whh  = (const float*)d_in[8];
    const float* bih  = (const float*)d_in[9];
    const float* bhh  = (const float*)d_in[10];
    const float* cw   = (const float*)d_in[11];
    const float* cb   = (const float*)d_in[12];
    float*       out  = (float*)d_out;
    (void)in_sizes; (void)n_in; (void)out_size;

    cudaFuncSetAttribute(attn_mma, cudaFuncAttributeMaxDynamicSharedMemorySize, SMEM_SZ);
    prep1<<<128, 256>>>(ipw, opw);
    prep2<<<97, 256>>>(wih, bih, bhh);
    attn_mma<<<N_TOT / 2, 512, SMEM_SZ>>>(x, mask);
    lstm_kernel<<<16, 256>>>(done, h0, c0, whh, cw, cb, out);
}